// round 1
// baseline (speedup 1.0000x reference)
#include <cuda_runtime.h>
#include <math_constants.h>
#include <math.h>

#define BATCH 4
#define SEQ   4096
#define NPTS  (BATCH*SEQ)   // 16384
#define DIM   256
#define KNN   16

// ---------------- scratch (device globals; no runtime allocation) ----------------
__device__ float g_feat[NPTS*DIM];                      // fp32 features
__device__ float g_sq[NPTS];                            // squared norms
__device__ float g_dist[(size_t)BATCH*SEQ*SEQ];         // 268 MB distance matrix
__device__ int   g_idx[NPTS*KNN];                       // global neighbor rows
__device__ float g_h  [NPTS*DIM];
__device__ float g_q  [NPTS*DIM];
__device__ float g_kf [NPTS*DIM];
__device__ float g_vf [NPTS*DIM];
__device__ float g_qg [NPTS*DIM];                       // q@g1 + g1_b
__device__ float g_kg1[NPTS*DIM];                       // kf@g1
__device__ float g_R  [(size_t)NPTS*KNN*DIM];           // relu(pre), 268 MB
__device__ float g_Sb [(size_t)NPTS*KNN*DIM];           // R@g2 + g2_b, 268 MB
__device__ float g_res[NPTS*DIM];

// ---------------- prep: split pos/feat, compute sq norms ----------------
__global__ void prep_kernel(const float* __restrict__ x, float* __restrict__ pos_out) {
    int r = blockIdx.x;
    const float* xr = x + (size_t)r * (3 + DIM);
    int t = threadIdx.x;  // 256
    __shared__ float red[256];
    if (t < 3) pos_out[r*3 + t] = xr[t];
    float f = xr[3 + t];
    g_feat[(size_t)r*DIM + t] = f;
    red[t] = f * f;
    __syncthreads();
    for (int s = 128; s > 0; s >>= 1) {
        if (t < s) red[t] += red[t + s];
        __syncthreads();
    }
    if (t == 0) g_sq[r] = red[0];
}

// ---------------- generic fp32 GEMM: C[nrows x 256] = A[nrows x 256] @ W[256 x 256] ----------------
// BM=64, BN=256 (full width), BK=16. 256 threads; each computes 4 rows x 16 cols.
template<bool HAS_BIAS, bool HAS_ADD>
__global__ void __launch_bounds__(256)
gemm256_kernel(const float* __restrict__ A, const float* __restrict__ W,
               const float* __restrict__ bias, const float* __restrict__ addsrc,
               float* __restrict__ C) {
    __shared__ float As[16][68];
    __shared__ float Ws[16][260];
    int t = threadIdx.x;
    int rowBase = blockIdx.x * 64;
    int ty = t >> 4, tx = t & 15;
    float acc[4][16];
#pragma unroll
    for (int i = 0; i < 4; i++)
#pragma unroll
        for (int j = 0; j < 16; j++) acc[i][j] = 0.f;

    int lr = t >> 2;           // A tile row 0..63
    int lk = (t & 3) * 4;      // A tile k offset

    for (int kb = 0; kb < 256; kb += 16) {
        float4 a4 = *(const float4*)(A + (size_t)(rowBase + lr)*256 + kb + lk);
        As[lk+0][lr] = a4.x; As[lk+1][lr] = a4.y; As[lk+2][lr] = a4.z; As[lk+3][lr] = a4.w;
#pragma unroll
        for (int qq = 0; qq < 4; qq++) {
            int flat = t*4 + qq*1024;
            int rw = flat >> 8, cw = flat & 255;
            float4 w4 = *(const float4*)(W + (size_t)(kb + rw)*256 + cw);
            *(float4*)&Ws[rw][cw] = w4;
        }
        __syncthreads();
#pragma unroll
        for (int k = 0; k < 16; k++) {
            float4 a = *(const float4*)&As[k][ty*4];
            float av[4] = {a.x, a.y, a.z, a.w};
            float bv[16];
#pragma unroll
            for (int qq = 0; qq < 4; qq++) {
                float4 b = *(const float4*)&Ws[k][tx*16 + qq*4];
                bv[qq*4+0] = b.x; bv[qq*4+1] = b.y; bv[qq*4+2] = b.z; bv[qq*4+3] = b.w;
            }
#pragma unroll
            for (int i = 0; i < 4; i++)
#pragma unroll
                for (int j = 0; j < 16; j++)
                    acc[i][j] += av[i] * bv[j];
        }
        __syncthreads();
    }
    // epilogue
#pragma unroll
    for (int i = 0; i < 4; i++) {
        int row = rowBase + ty*4 + i;
#pragma unroll
        for (int qq = 0; qq < 4; qq++) {
            int col = tx*16 + qq*4;
            float4 v;
            float vv[4];
#pragma unroll
            for (int e = 0; e < 4; e++) {
                float val = acc[i][qq*4 + e];
                if (HAS_BIAS) val += bias[col + e];
                if (HAS_ADD)  val += addsrc[(size_t)row*256 + col + e];
                vv[e] = val;
            }
            v.x = vv[0]; v.y = vv[1]; v.z = vv[2]; v.w = vv[3];
            *(float4*)(C + (size_t)row*256 + col) = v;
        }
    }
}

// ---------------- distance GEMM (symmetric, upper-tri tiles only) ----------------
// dist[b][i][j] = sq_i + sq_j - 2 * dot(feat_i, feat_j)
__global__ void __launch_bounds__(256)
dist_kernel() {
    int b = blockIdx.y;
    const float* A   = g_feat + (size_t)b * SEQ * DIM;
    const float* sqb = g_sq   + (size_t)b * SEQ;
    float* Dmat      = g_dist + (size_t)b * SEQ * SEQ;

    // linear pid -> (ti, tj) with tj >= ti over 64x64 tiles
    int pid = blockIdx.x;
    int ti = 0;
    while (pid >= 64 - ti) { pid -= 64 - ti; ti++; }
    int tj = ti + pid;
    int i0 = ti * 64, j0 = tj * 64;

    __shared__ float As[16][68];
    __shared__ float Bs[16][68];
    __shared__ float Ts[64][68];

    int t = threadIdx.x;
    int ty = t >> 4, tx = t & 15;
    float acc[4][4];
#pragma unroll
    for (int i = 0; i < 4; i++)
#pragma unroll
        for (int j = 0; j < 4; j++) acc[i][j] = 0.f;

    int lr = t >> 2, lk = (t & 3) * 4;

    for (int kb = 0; kb < 256; kb += 16) {
        float4 a4 = *(const float4*)(A + (size_t)(i0 + lr)*256 + kb + lk);
        As[lk+0][lr] = a4.x; As[lk+1][lr] = a4.y; As[lk+2][lr] = a4.z; As[lk+3][lr] = a4.w;
        float4 b4 = *(const float4*)(A + (size_t)(j0 + lr)*256 + kb + lk);
        Bs[lk+0][lr] = b4.x; Bs[lk+1][lr] = b4.y; Bs[lk+2][lr] = b4.z; Bs[lk+3][lr] = b4.w;
        __syncthreads();
#pragma unroll
        for (int k = 0; k < 16; k++) {
            float4 a = *(const float4*)&As[k][ty*4];
            float4 bb = *(const float4*)&Bs[k][tx*4];
            float av[4] = {a.x, a.y, a.z, a.w};
            float bv[4] = {bb.x, bb.y, bb.z, bb.w};
#pragma unroll
            for (int i = 0; i < 4; i++)
#pragma unroll
                for (int j = 0; j < 4; j++)
                    acc[i][j] += av[i] * bv[j];
        }
        __syncthreads();
    }

    float si[4], sj[4];
#pragma unroll
    for (int i = 0; i < 4; i++) si[i] = sqb[i0 + ty*4 + i];
#pragma unroll
    for (int j = 0; j < 4; j++) sj[j] = sqb[j0 + tx*4 + j];

#pragma unroll
    for (int i = 0; i < 4; i++) {
        int row = i0 + ty*4 + i;
        float4 v;
        float d0 = si[i] + sj[0] - 2.f*acc[i][0];
        float d1 = si[i] + sj[1] - 2.f*acc[i][1];
        float d2 = si[i] + sj[2] - 2.f*acc[i][2];
        float d3 = si[i] + sj[3] - 2.f*acc[i][3];
        v.x = d0; v.y = d1; v.z = d2; v.w = d3;
        *(float4*)(Dmat + (size_t)row*SEQ + j0 + tx*4) = v;
        Ts[ty*4+i][tx*4+0] = d0; Ts[ty*4+i][tx*4+1] = d1;
        Ts[ty*4+i][tx*4+2] = d2; Ts[ty*4+i][tx*4+3] = d3;
    }
    __syncthreads();
    if (ti != tj) {
        int r2 = t >> 2;            // local j row 0..63
        int c0 = (t & 3) * 16;      // local i col start
#pragma unroll
        for (int qq = 0; qq < 4; qq++) {
            float4 o;
            o.x = Ts[c0 + qq*4 + 0][r2];
            o.y = Ts[c0 + qq*4 + 1][r2];
            o.z = Ts[c0 + qq*4 + 2][r2];
            o.w = Ts[c0 + qq*4 + 3][r2];
            *(float4*)(Dmat + (size_t)(j0 + r2)*SEQ + i0 + c0 + qq*4) = o;
        }
    }
}

// ---------------- top-K (K=16 smallest) per row; warp per row ----------------
__global__ void __launch_bounds__(128)
topk_kernel() {
    __shared__ float sv[4][512];
    __shared__ int   si[4][512];
    int w = threadIdx.x >> 5, lane = threadIdx.x & 31;
    int r = blockIdx.x * 4 + w;
    int b = r >> 12, i = r & (SEQ - 1);
    const float* row = g_dist + ((size_t)b*SEQ + i)*SEQ;

    float v[16]; int id[16];
#pragma unroll
    for (int t = 0; t < 16; t++) { v[t] = CUDART_INF_F; id[t] = -1; }

    for (int j = lane; j < SEQ; j += 32) {
        float d = row[j];
        if (d < v[15]) {
            float cv = d; int ci = j;
#pragma unroll
            for (int t = 0; t < 16; t++) {
                if (cv < v[t]) {
                    float tv = v[t]; v[t] = cv; cv = tv;
                    int ti2 = id[t]; id[t] = ci; ci = ti2;
                }
            }
        }
    }
#pragma unroll
    for (int t = 0; t < 16; t++) { sv[w][lane*16 + t] = v[t]; si[w][lane*16 + t] = id[t]; }
    __syncwarp();

    int p = 0;
    for (int it = 0; it < 16; ++it) {
        float cand = (p < 16) ? sv[w][lane*16 + p] : CUDART_INF_F;
        float bv = cand; int bl = lane;
#pragma unroll
        for (int off = 16; off; off >>= 1) {
            float ov = __shfl_xor_sync(0xffffffffu, bv, off);
            int   ol = __shfl_xor_sync(0xffffffffu, bl, off);
            if (ov < bv || (ov == bv && ol < bl)) { bv = ov; bl = ol; }
        }
        if (lane == bl) {
            g_idx[r*16 + it] = b*SEQ + si[w][lane*16 + p];
            p++;
        }
    }
}

// ---------------- build R = relu(qg[m] - kg1[idx[m][n]]) ----------------
__global__ void rbuild_kernel() {
    int r = blockIdx.x;
    int t = threadIdx.x;  // 256
    __shared__ float qs[256];
    __shared__ int   is_[16];
    qs[t] = g_qg[(size_t)r*256 + t];
    if (t < 16) is_[t] = g_idx[r*16 + t];
    __syncthreads();
#pragma unroll
    for (int n = 0; n < 16; n++) {
        float val = qs[t] - g_kg1[(size_t)is_[n]*256 + t];
        g_R[((size_t)r*16 + n)*256 + t] = fmaxf(val, 0.f);
    }
}

// ---------------- softmax over neighbors + weighted sum of v ----------------
__global__ void softres_kernel() {
    int r = blockIdx.x;
    int t = threadIdx.x;  // f = 0..255
    __shared__ int is_[16];
    if (t < 16) is_[t] = g_idx[r*16 + t];
    __syncthreads();
    float s[16];
    float mx = -CUDART_INF_F;
#pragma unroll
    for (int n = 0; n < 16; n++) {
        s[n] = g_Sb[((size_t)r*16 + n)*256 + t];
        mx = fmaxf(mx, s[n]);
    }
    float sum = 0.f;
#pragma unroll
    for (int n = 0; n < 16; n++) {
        float wv = __expf((s[n] - mx) * 0.0625f);  // 1/sqrt(256)
        s[n] = wv; sum += wv;
    }
    float res = 0.f;
#pragma unroll
    for (int n = 0; n < 16; n++)
        res += s[n] * g_vf[(size_t)is_[n]*256 + t];
    g_res[(size_t)r*256 + t] = res / sum;
}

// ---------------- launch ----------------
extern "C" void kernel_launch(void* const* d_in, const int* in_sizes, int n_in,
                              void* d_out, int out_size) {
    const float* x     = (const float*)d_in[0];
    const float* fc1_w = (const float*)d_in[1];
    const float* fc1_b = (const float*)d_in[2];
    const float* fc2_w = (const float*)d_in[3];
    const float* fc2_b = (const float*)d_in[4];
    const float* wq_w  = (const float*)d_in[5];
    const float* wk_w  = (const float*)d_in[6];
    const float* wv_w  = (const float*)d_in[7];
    const float* g1_w  = (const float*)d_in[8];
    const float* g1_b  = (const float*)d_in[9];
    const float* g2_w  = (const float*)d_in[10];
    const float* g2_b  = (const float*)d_in[11];
    float* out = (float*)d_out;

    float *p_feat, *p_h, *p_q, *p_kf, *p_vf, *p_qg, *p_kg1, *p_R, *p_Sb, *p_res;
    cudaGetSymbolAddress((void**)&p_feat, g_feat);
    cudaGetSymbolAddress((void**)&p_h,    g_h);
    cudaGetSymbolAddress((void**)&p_q,    g_q);
    cudaGetSymbolAddress((void**)&p_kf,   g_kf);
    cudaGetSymbolAddress((void**)&p_vf,   g_vf);
    cudaGetSymbolAddress((void**)&p_qg,   g_qg);
    cudaGetSymbolAddress((void**)&p_kg1,  g_kg1);
    cudaGetSymbolAddress((void**)&p_R,    g_R);
    cudaGetSymbolAddress((void**)&p_Sb,   g_Sb);
    cudaGetSymbolAddress((void**)&p_res,  g_res);

    prep_kernel<<<NPTS, 256>>>(x, out);

    // distance + topk (depends only on feat/sq)
    dist_kernel<<<dim3(2080, BATCH), 256>>>();
    topk_kernel<<<NPTS/4, 128>>>();

    // attention-branch GEMMs (independent of dist; serialized on stream anyway)
    gemm256_kernel<true,  false><<<NPTS/64, 256>>>(p_feat, fc1_w, fc1_b, nullptr, p_h);
    gemm256_kernel<false, false><<<NPTS/64, 256>>>(p_h, wq_w, nullptr, nullptr, p_q);
    gemm256_kernel<false, false><<<NPTS/64, 256>>>(p_h, wk_w, nullptr, nullptr, p_kf);
    gemm256_kernel<false, false><<<NPTS/64, 256>>>(p_h, wv_w, nullptr, nullptr, p_vf);
    gemm256_kernel<true,  false><<<NPTS/64, 256>>>(p_q,  g1_w, g1_b, nullptr, p_qg);
    gemm256_kernel<false, false><<<NPTS/64, 256>>>(p_kf, g1_w, nullptr, nullptr, p_kg1);

    // R = relu(qg - gather(kg1)), then big GEMM R @ g2 + g2_b
    rbuild_kernel<<<NPTS, 256>>>();
    gemm256_kernel<true, false><<<(NPTS*KNN)/64, 256>>>(p_R, g2_w, g2_b, nullptr, p_Sb);

    // softmax over neighbors + weighted v-sum
    softres_kernel<<<NPTS, 256>>>();

    // out = res @ fc2 + fc2_b + feat
    gemm256_kernel<true, true><<<NPTS/64, 256>>>(p_res, fc2_w, fc2_b, p_feat, out + NPTS*3);
}

// round 3
// speedup vs baseline: 3.7880x; 3.7880x over previous
#include <cuda_runtime.h>
#include <cuda_bf16.h>
#include <math_constants.h>
#include <math.h>
#include <stdint.h>

#define BATCH 4
#define SEQ   4096
#define NPTS  (BATCH*SEQ)   // 16384
#define DIM   256
#define KNN   16

typedef __nv_bfloat16 bf16;

// ---------------- scratch ----------------
__device__ float g_feat[NPTS*DIM];
__device__ bf16  g_fhi[NPTS*DIM];
__device__ bf16  g_flo[NPTS*DIM];
__device__ float g_sq[NPTS];
__device__ float g_dist[(size_t)BATCH*SEQ*SEQ];   // 268 MB
__device__ int   g_idx[NPTS*KNN];
__device__ bf16  g_h  [NPTS*DIM];
__device__ bf16  g_vf [NPTS*DIM];
__device__ float g_qg [NPTS*DIM];
__device__ float g_kg1[NPTS*DIM];
__device__ bf16  g_Rb [(size_t)NPTS*KNN*DIM];     // 134 MB
__device__ bf16  g_Sbb[(size_t)NPTS*KNN*DIM];     // 134 MB
__device__ bf16  g_resb[NPTS*DIM];
// bf16 weights
__device__ bf16 g_fc1b[DIM*DIM], g_wqb[DIM*DIM], g_wkb[DIM*DIM], g_wvb[DIM*DIM];
__device__ bf16 g_g1b[DIM*DIM], g_g2b[DIM*DIM], g_fc2b[DIM*DIM];
__device__ bf16 g_wq1[DIM*DIM], g_wk1[DIM*DIM];   // composed wq@g1, wk@g1

// ---------------- helpers ----------------
__device__ __forceinline__ uint32_t smem_u32(const void* p) {
    return (uint32_t)__cvta_generic_to_shared(p);
}
__device__ __forceinline__ void ldsm_x4(uint32_t addr, uint32_t& r0, uint32_t& r1, uint32_t& r2, uint32_t& r3) {
    asm volatile("ldmatrix.sync.aligned.m8n8.x4.shared.b16 {%0,%1,%2,%3}, [%4];"
                 : "=r"(r0), "=r"(r1), "=r"(r2), "=r"(r3) : "r"(addr));
}
__device__ __forceinline__ void ldsm_x4_t(uint32_t addr, uint32_t& r0, uint32_t& r1, uint32_t& r2, uint32_t& r3) {
    asm volatile("ldmatrix.sync.aligned.m8n8.x4.trans.shared.b16 {%0,%1,%2,%3}, [%4];"
                 : "=r"(r0), "=r"(r1), "=r"(r2), "=r"(r3) : "r"(addr));
}
__device__ __forceinline__ void mma_bf16(float* c, const uint32_t* a, const uint32_t* b) {
    asm volatile("mma.sync.aligned.m16n8k16.row.col.f32.bf16.bf16.f32 "
                 "{%0,%1,%2,%3},{%4,%5,%6,%7},{%8,%9},{%0,%1,%2,%3};"
                 : "+f"(c[0]), "+f"(c[1]), "+f"(c[2]), "+f"(c[3])
                 : "r"(a[0]), "r"(a[1]), "r"(a[2]), "r"(a[3]), "r"(b[0]), "r"(b[1]));
}

// ---------------- weight conversion ----------------
__global__ void cvt_kernel(const float* __restrict__ s, bf16* __restrict__ d) {
    int i = (blockIdx.x * 256 + threadIdx.x) * 4;
    float4 v = *(const float4*)(s + i);
    d[i+0] = __float2bfloat16_rn(v.x);
    d[i+1] = __float2bfloat16_rn(v.y);
    d[i+2] = __float2bfloat16_rn(v.z);
    d[i+3] = __float2bfloat16_rn(v.w);
}

// ---------------- prep ----------------
__global__ void prep_kernel(const float* __restrict__ x, float* __restrict__ pos_out) {
    int r = blockIdx.x;
    const float* xr = x + (size_t)r * (3 + DIM);
    int t = threadIdx.x;
    __shared__ float red[256];
    if (t < 3) pos_out[r*3 + t] = xr[t];
    float f = xr[3 + t];
    g_feat[(size_t)r*DIM + t] = f;
    bf16 hi = __float2bfloat16_rn(f);
    g_fhi[(size_t)r*DIM + t] = hi;
    g_flo[(size_t)r*DIM + t] = __float2bfloat16_rn(f - __bfloat162float(hi));
    red[t] = f * f;
    __syncthreads();
    for (int s = 128; s > 0; s >>= 1) {
        if (t < s) red[t] += red[t + s];
        __syncthreads();
    }
    if (t == 0) g_sq[r] = red[0];
}

// ---------------- bf16 tensor-core GEMM: C[Mx256] = A[Mx256] @ W[256x256] ----------------
// BM=128, BN=128, BK=32, 8 warps (4 m x 2 n), warp tile 32x64.
template<bool HAS_BIAS, bool HAS_ADD, bool OUT_BF16>
__global__ void __launch_bounds__(256)
mma_gemm(const bf16* __restrict__ Ag, const bf16* __restrict__ Wg,
         const float* __restrict__ bias, const float* __restrict__ addsrc,
         void* __restrict__ Cout) {
    __shared__ bf16 As[128][40];
    __shared__ bf16 Ws_[32][136];
    int t = threadIdx.x;
    int lane = t & 31, w = t >> 5;
    int wm = w & 3, wn = w >> 2;
    int m0 = blockIdx.x * 128;
    int n0 = blockIdx.y * 128;

    float acc[2][8][4];
#pragma unroll
    for (int mi = 0; mi < 2; mi++)
#pragma unroll
        for (int nj = 0; nj < 8; nj++)
#pragma unroll
            for (int e = 0; e < 4; e++) acc[mi][nj][e] = 0.f;

    for (int kb = 0; kb < 256; kb += 32) {
#pragma unroll
        for (int q = 0; q < 2; q++) {
            int flat = t * 2 + q;                 // 512 uint4 for A (128x32)
            int row = flat >> 2, col = (flat & 3) * 8;
            *(uint4*)&As[row][col] = *(const uint4*)(Ag + ((size_t)(m0 + row) * 256 + kb + col));
        }
#pragma unroll
        for (int q = 0; q < 2; q++) {
            int flat = t * 2 + q;                 // 512 uint4 for W (32x128)
            int row = flat >> 4, col = (flat & 15) * 8;
            *(uint4*)&Ws_[row][col] = *(const uint4*)(Wg + ((size_t)(kb + row) * 256 + n0 + col));
        }
        __syncthreads();
#pragma unroll
        for (int kk = 0; kk < 32; kk += 16) {
            uint32_t a[2][4], bfr[8][2];
#pragma unroll
            for (int mi = 0; mi < 2; mi++) {
                uint32_t addr = smem_u32(&As[wm*32 + mi*16 + (lane & 15)][kk + (lane >> 4) * 8]);
                ldsm_x4(addr, a[mi][0], a[mi][1], a[mi][2], a[mi][3]);
            }
#pragma unroll
            for (int g = 0; g < 4; g++) {
                uint32_t r0, r1, r2, r3;
                uint32_t addr = smem_u32(&Ws_[kk + (lane & 15)][wn*64 + g*16 + (lane >> 4) * 8]);
                ldsm_x4_t(addr, r0, r1, r2, r3);
                bfr[g*2][0] = r0; bfr[g*2][1] = r1;
                bfr[g*2+1][0] = r2; bfr[g*2+1][1] = r3;
            }
#pragma unroll
            for (int mi = 0; mi < 2; mi++)
#pragma unroll
                for (int nj = 0; nj < 8; nj++)
                    mma_bf16(acc[mi][nj], a[mi], bfr[nj]);
        }
        __syncthreads();
    }

    // epilogue
#pragma unroll
    for (int mi = 0; mi < 2; mi++) {
#pragma unroll
        for (int nj = 0; nj < 8; nj++) {
            int r = m0 + wm*32 + mi*16 + (lane >> 2);
            int cc = n0 + wn*64 + nj*8 + (lane & 3) * 2;
            float v0 = acc[mi][nj][0], v1 = acc[mi][nj][1];
            float v2 = acc[mi][nj][2], v3 = acc[mi][nj][3];
            if (HAS_BIAS) {
                float b0 = bias[cc], b1 = bias[cc+1];
                v0 += b0; v1 += b1; v2 += b0; v3 += b1;
            }
            if (HAS_ADD) {
                v0 += addsrc[(size_t)r*256 + cc];     v1 += addsrc[(size_t)r*256 + cc + 1];
                v2 += addsrc[(size_t)(r+8)*256 + cc]; v3 += addsrc[(size_t)(r+8)*256 + cc + 1];
            }
            if (OUT_BF16) {
                bf16* C = (bf16*)Cout;
                __nv_bfloat162 o0, o1;
                o0.x = __float2bfloat16_rn(v0); o0.y = __float2bfloat16_rn(v1);
                o1.x = __float2bfloat16_rn(v2); o1.y = __float2bfloat16_rn(v3);
                *(__nv_bfloat162*)(C + (size_t)r*256 + cc) = o0;
                *(__nv_bfloat162*)(C + (size_t)(r+8)*256 + cc) = o1;
            } else {
                float* C = (float*)Cout;
                float2 o0 = {v0, v1}, o1 = {v2, v3};
                *(float2*)(C + (size_t)r*256 + cc) = o0;
                *(float2*)(C + (size_t)(r+8)*256 + cc) = o1;
            }
        }
    }
}

// ---------------- distance via split-bf16 tensor cores ----------------
// dist = sq_i + sq_j - 2*(hi_i.hi_j + hi_i.lo_j + lo_i.hi_j)
// Upper-tri 128x128 tiles; mirror written via smem-staged coalesced transpose.
__global__ void __launch_bounds__(256)
dist_mma_kernel() {
    __shared__ union {
        struct { bf16 ah[128][40], al[128][40], bh[128][40], bl[128][40]; } t;
        float ts[64][132];
    } sm;

    int b = blockIdx.y;
    const bf16* FH = g_fhi + (size_t)b * SEQ * DIM;
    const bf16* FL = g_flo + (size_t)b * SEQ * DIM;
    const float* sqb = g_sq + (size_t)b * SEQ;
    float* Dmat = g_dist + (size_t)b * SEQ * SEQ;

    int pid = blockIdx.x;   // 0..527 -> upper-tri (ti,tj), T=32
    int ti = 0;
    while (pid >= 32 - ti) { pid -= 32 - ti; ti++; }
    int tj = ti + pid;
    int i0 = ti * 128, j0 = tj * 128;

    int t = threadIdx.x;
    int lane = t & 31, w = t >> 5;
    int wm = w & 3, wn = w >> 2;

    float acc[2][8][4];
#pragma unroll
    for (int mi = 0; mi < 2; mi++)
#pragma unroll
        for (int nj = 0; nj < 8; nj++)
#pragma unroll
            for (int e = 0; e < 4; e++) acc[mi][nj][e] = 0.f;

    for (int kb = 0; kb < 256; kb += 32) {
#pragma unroll
        for (int q = 0; q < 2; q++) {
            int flat = t * 2 + q;
            int row = flat >> 2, col = (flat & 3) * 8;
            size_t offA = (size_t)(i0 + row) * 256 + kb + col;
            size_t offB = (size_t)(j0 + row) * 256 + kb + col;
            *(uint4*)&sm.t.ah[row][col] = *(const uint4*)(FH + offA);
            *(uint4*)&sm.t.al[row][col] = *(const uint4*)(FL + offA);
            *(uint4*)&sm.t.bh[row][col] = *(const uint4*)(FH + offB);
            *(uint4*)&sm.t.bl[row][col] = *(const uint4*)(FL + offB);
        }
        __syncthreads();
#pragma unroll
        for (int kk = 0; kk < 32; kk += 16) {
            uint32_t ah[2][4], al[2][4], bh[8][2], bl[8][2];
#pragma unroll
            for (int mi = 0; mi < 2; mi++) {
                uint32_t addr = smem_u32(&sm.t.ah[wm*32 + mi*16 + (lane & 15)][kk + (lane >> 4) * 8]);
                ldsm_x4(addr, ah[mi][0], ah[mi][1], ah[mi][2], ah[mi][3]);
                addr = smem_u32(&sm.t.al[wm*32 + mi*16 + (lane & 15)][kk + (lane >> 4) * 8]);
                ldsm_x4(addr, al[mi][0], al[mi][1], al[mi][2], al[mi][3]);
            }
#pragma unroll
            for (int g = 0; g < 4; g++) {
                int nrow = wn*64 + g*16 + (lane & 7) + ((lane >> 4) << 3);
                int ncol = kk + ((lane >> 3) & 1) * 8;
                uint32_t r0, r1, r2, r3;
                ldsm_x4(smem_u32(&sm.t.bh[nrow][ncol]), r0, r1, r2, r3);
                bh[g*2][0] = r0; bh[g*2][1] = r1; bh[g*2+1][0] = r2; bh[g*2+1][1] = r3;
                ldsm_x4(smem_u32(&sm.t.bl[nrow][ncol]), r0, r1, r2, r3);
                bl[g*2][0] = r0; bl[g*2][1] = r1; bl[g*2+1][0] = r2; bl[g*2+1][1] = r3;
            }
#pragma unroll
            for (int mi = 0; mi < 2; mi++)
#pragma unroll
                for (int nj = 0; nj < 8; nj++) {
                    mma_bf16(acc[mi][nj], ah[mi], bh[nj]);
                    mma_bf16(acc[mi][nj], ah[mi], bl[nj]);
                    mma_bf16(acc[mi][nj], al[mi], bh[nj]);
                }
        }
        __syncthreads();
    }

    // epilogue: d = sq_i + sq_j - 2*dot ; direct write + staged mirror
#pragma unroll
    for (int mi = 0; mi < 2; mi++) {
        int r = i0 + wm*32 + mi*16 + (lane >> 2);
        float si0 = sqb[r], si1 = sqb[r + 8];
#pragma unroll
        for (int nj = 0; nj < 8; nj++) {
            int cc = j0 + wn*64 + nj*8 + (lane & 3) * 2;
            float sj0 = sqb[cc], sj1 = sqb[cc + 1];
            float d0 = si0 + sj0 - 2.f * acc[mi][nj][0];
            float d1 = si0 + sj1 - 2.f * acc[mi][nj][1];
            float d2 = si1 + sj0 - 2.f * acc[mi][nj][2];
            float d3 = si1 + sj1 - 2.f * acc[mi][nj][3];
            acc[mi][nj][0] = d0; acc[mi][nj][1] = d1;
            acc[mi][nj][2] = d2; acc[mi][nj][3] = d3;
            float2 o0 = {d0, d1}, o1 = {d2, d3};
            *(float2*)(Dmat + (size_t)r * SEQ + cc) = o0;
            *(float2*)(Dmat + (size_t)(r + 8) * SEQ + cc) = o1;
        }
    }
    if (ti != tj) {
        __syncthreads();   // done with operand smem
#pragma unroll
        for (int p = 0; p < 2; p++) {
            if (wn == p) {
#pragma unroll
                for (int mi = 0; mi < 2; mi++) {
                    int lm = wm*32 + mi*16 + (lane >> 2);
#pragma unroll
                    for (int nj = 0; nj < 8; nj++) {
                        int ln = nj*8 + (lane & 3) * 2;
                        sm.ts[ln][lm]       = acc[mi][nj][0];
                        sm.ts[ln+1][lm]     = acc[mi][nj][1];
                        sm.ts[ln][lm+8]     = acc[mi][nj][2];
                        sm.ts[ln+1][lm+8]   = acc[mi][nj][3];
                    }
                }
            }
            __syncthreads();
#pragma unroll
            for (int qq = 0; qq < 8; qq++) {
                int flat = t + qq * 256;      // 2048 float4 = 64 rows x 32 float4
                int rj = flat >> 5;
                int c4 = (flat & 31) * 4;
                float4 v = *(float4*)&sm.ts[rj][c4];
                *(float4*)(Dmat + (size_t)(j0 + p*64 + rj) * SEQ + i0 + c4) = v;
            }
            __syncthreads();
        }
    }
}

// ---------------- top-K ----------------
__global__ void __launch_bounds__(128)
topk_kernel() {
    __shared__ float sv[4][512];
    __shared__ int   si[4][512];
    int w = threadIdx.x >> 5, lane = threadIdx.x & 31;
    int r = blockIdx.x * 4 + w;
    int b = r >> 12, i = r & (SEQ - 1);
    const float* row = g_dist + ((size_t)b*SEQ + i)*SEQ;

    float v[16]; int id[16];
#pragma unroll
    for (int t = 0; t < 16; t++) { v[t] = CUDART_INF_F; id[t] = -1; }

    for (int j = lane; j < SEQ; j += 32) {
        float d = row[j];
        if (d < v[15]) {
            float cv = d; int ci = j;
#pragma unroll
            for (int t = 0; t < 16; t++) {
                if (cv < v[t]) {
                    float tv = v[t]; v[t] = cv; cv = tv;
                    int ti2 = id[t]; id[t] = ci; ci = ti2;
                }
            }
        }
    }
#pragma unroll
    for (int t = 0; t < 16; t++) { sv[w][lane*16 + t] = v[t]; si[w][lane*16 + t] = id[t]; }
    __syncwarp();

    int p = 0;
    for (int it = 0; it < 16; ++it) {
        float cand = (p < 16) ? sv[w][lane*16 + p] : CUDART_INF_F;
        float bv = cand; int bl = lane;
#pragma unroll
        for (int off = 16; off; off >>= 1) {
            float ov = __shfl_xor_sync(0xffffffffu, bv, off);
            int   ol = __shfl_xor_sync(0xffffffffu, bl, off);
            if (ov < bv || (ov == bv && ol < bl)) { bv = ov; bl = ol; }
        }
        if (lane == bl) {
            g_idx[r*16 + it] = b*SEQ + si[w][lane*16 + p];
            p++;
        }
    }
}

// ---------------- R = relu(qg[m] - kg1[idx]) -> bf16 ----------------
__global__ void rbuild_kernel() {
    int r = blockIdx.x;
    int t = threadIdx.x;
    __shared__ float qs[256];
    __shared__ int   is_[16];
    qs[t] = g_qg[(size_t)r*256 + t];
    if (t < 16) is_[t] = g_idx[r*16 + t];
    __syncthreads();
#pragma unroll
    for (int n = 0; n < 16; n++) {
        float val = qs[t] - g_kg1[(size_t)is_[n]*256 + t];
        g_Rb[((size_t)r*16 + n)*256 + t] = __float2bfloat16_rn(fmaxf(val, 0.f));
    }
}

// ---------------- softmax + weighted v-sum -> res (bf16) ----------------
__global__ void softres_kernel() {
    int r = blockIdx.x;
    int t = threadIdx.x;
    __shared__ int is_[16];
    if (t < 16) is_[t] = g_idx[r*16 + t];
    __syncthreads();
    float s[16];
    float mx = -CUDART_INF_F;
#pragma unroll
    for (int n = 0; n < 16; n++) {
        s[n] = __bfloat162float(g_Sbb[((size_t)r*16 + n)*256 + t]);
        mx = fmaxf(mx, s[n]);
    }
    float sum = 0.f;
#pragma unroll
    for (int n = 0; n < 16; n++) {
        float wv = __expf((s[n] - mx) * 0.0625f);
        s[n] = wv; sum += wv;
    }
    float res = 0.f;
#pragma unroll
    for (int n = 0; n < 16; n++)
        res += s[n] * __bfloat162float(g_vf[(size_t)is_[n]*256 + t]);
    g_resb[(size_t)r*256 + t] = __float2bfloat16_rn(res / sum);
}

// ---------------- launch ----------------
extern "C" void kernel_launch(void* const* d_in, const int* in_sizes, int n_in,
                              void* d_out, int out_size) {
    const float* x     = (const float*)d_in[0];
    const float* fc1_w = (const float*)d_in[1];
    const float* fc1_b = (const float*)d_in[2];
    const float* fc2_w = (const float*)d_in[3];
    const float* fc2_b = (const float*)d_in[4];
    const float* wq_w  = (const float*)d_in[5];
    const float* wk_w  = (const float*)d_in[6];
    const float* wv_w  = (const float*)d_in[7];
    const float* g1_w  = (const float*)d_in[8];
    const float* g1_b  = (const float*)d_in[9];
    const float* g2_w  = (const float*)d_in[10];
    const float* g2_b  = (const float*)d_in[11];
    float* out = (float*)d_out;

    bf16 *p_fc1b, *p_wqb, *p_wkb, *p_wvb, *p_g1b, *p_g2b, *p_fc2b, *p_wq1, *p_wk1;
    bf16 *p_fhi, *p_h, *p_vf, *p_Rb, *p_Sbb, *p_resb;
    float *p_feat, *p_qg, *p_kg1;
    cudaGetSymbolAddress((void**)&p_fc1b, g_fc1b);
    cudaGetSymbolAddress((void**)&p_wqb,  g_wqb);
    cudaGetSymbolAddress((void**)&p_wkb,  g_wkb);
    cudaGetSymbolAddress((void**)&p_wvb,  g_wvb);
    cudaGetSymbolAddress((void**)&p_g1b,  g_g1b);
    cudaGetSymbolAddress((void**)&p_g2b,  g_g2b);
    cudaGetSymbolAddress((void**)&p_fc2b, g_fc2b);
    cudaGetSymbolAddress((void**)&p_wq1,  g_wq1);
    cudaGetSymbolAddress((void**)&p_wk1,  g_wk1);
    cudaGetSymbolAddress((void**)&p_fhi,  g_fhi);
    cudaGetSymbolAddress((void**)&p_h,    g_h);
    cudaGetSymbolAddress((void**)&p_vf,   g_vf);
    cudaGetSymbolAddress((void**)&p_Rb,   g_Rb);
    cudaGetSymbolAddress((void**)&p_Sbb,  g_Sbb);
    cudaGetSymbolAddress((void**)&p_resb, g_resb);
    cudaGetSymbolAddress((void**)&p_feat, g_feat);
    cudaGetSymbolAddress((void**)&p_qg,   g_qg);
    cudaGetSymbolAddress((void**)&p_kg1,  g_kg1);

    // weight conversions (64 blocks x 256 thr x 4 elems = 65536)
    cvt_kernel<<<64, 256>>>(fc1_w, p_fc1b);
    cvt_kernel<<<64, 256>>>(wq_w,  p_wqb);
    cvt_kernel<<<64, 256>>>(wk_w,  p_wkb);
    cvt_kernel<<<64, 256>>>(wv_w,  p_wvb);
    cvt_kernel<<<64, 256>>>(g1_w,  p_g1b);
    cvt_kernel<<<64, 256>>>(g2_w,  p_g2b);
    cvt_kernel<<<64, 256>>>(fc2_w, p_fc2b);

    prep_kernel<<<NPTS, 256>>>(x, out);

    // composed weights: Wq1 = wq@g1, Wk1 = wk@g1
    mma_gemm<false, false, true><<<dim3(2, 2), 256>>>(p_wqb, p_g1b, nullptr, nullptr, p_wq1);
    mma_gemm<false, false, true><<<dim3(2, 2), 256>>>(p_wkb, p_g1b, nullptr, nullptr, p_wk1);

    // distance + topk
    dist_mma_kernel<<<dim3(528, BATCH), 256>>>();
    topk_kernel<<<NPTS/4, 128>>>();

    // h = feat@fc1 + b ; vf = h@wv ; qg = h@Wq1 + g1_b ; kg1 = h@Wk1
    mma_gemm<true,  false, true ><<<dim3(NPTS/128, 2), 256>>>(p_fhi, p_fc1b, fc1_b, nullptr, p_h);
    mma_gemm<false, false, true ><<<dim3(NPTS/128, 2), 256>>>(p_h, p_wvb, nullptr, nullptr, p_vf);
    mma_gemm<true,  false, false><<<dim3(NPTS/128, 2), 256>>>(p_h, p_wq1, g1_b, nullptr, p_qg);
    mma_gemm<false, false, false><<<dim3(NPTS/128, 2), 256>>>(p_h, p_wk1, nullptr, nullptr, p_kg1);

    // R = relu(qg - gather(kg1)) ; Sb = R@g2 + g2_b
    rbuild_kernel<<<NPTS, 256>>>();
    mma_gemm<true, false, true><<<dim3((NPTS*KNN)/128, 2), 256>>>(p_Rb, p_g2b, g2_b, nullptr, p_Sbb);

    // softmax + weighted v-sum
    softres_kernel<<<NPTS, 256>>>();

    // out = res@fc2 + fc2_b + feat
    mma_gemm<true, true, false><<<dim3(NPTS/128, 2), 256>>>(p_resb, p_fc2b, fc2_b, p_feat, out + (size_t)NPTS*3);
}

// round 5
// speedup vs baseline: 4.1188x; 1.0873x over previous
#include <cuda_runtime.h>
#include <cuda_bf16.h>
#include <math_constants.h>
#include <math.h>
#include <stdint.h>

#define BATCH 4
#define SEQ   4096
#define NPTS  (BATCH*SEQ)   // 16384
#define DIM   256
#define KNN   16

typedef __nv_bfloat16 bf16;

// ---------------- scratch ----------------
__device__ float g_feat[NPTS*DIM];
__device__ bf16  g_fhi[NPTS*DIM];
__device__ bf16  g_flo[NPTS*DIM];
__device__ float g_sq[NPTS];
__device__ float g_dist[(size_t)BATCH*SEQ*SEQ];   // 268 MB
__device__ int   g_idx[NPTS*KNN];
__device__ bf16  g_h  [NPTS*DIM];
__device__ bf16  g_vf [NPTS*DIM];
__device__ bf16  g_qgb [NPTS*DIM];
__device__ bf16  g_kg1b[NPTS*DIM];
__device__ bf16  g_resb[NPTS*DIM];
// bf16 weights
__device__ bf16 g_fc1b[DIM*DIM], g_wqb[DIM*DIM], g_wkb[DIM*DIM], g_wvb[DIM*DIM];
__device__ bf16 g_g1b[DIM*DIM], g_g2b[DIM*DIM], g_fc2b[DIM*DIM];
__device__ bf16 g_wq1[DIM*DIM], g_wk1[DIM*DIM];   // composed wq@g1, wk@g1

// ---------------- helpers ----------------
__device__ __forceinline__ uint32_t smem_u32(const void* p) {
    return (uint32_t)__cvta_generic_to_shared(p);
}
__device__ __forceinline__ void ldsm_x4(uint32_t addr, uint32_t& r0, uint32_t& r1, uint32_t& r2, uint32_t& r3) {
    asm volatile("ldmatrix.sync.aligned.m8n8.x4.shared.b16 {%0,%1,%2,%3}, [%4];"
                 : "=r"(r0), "=r"(r1), "=r"(r2), "=r"(r3) : "r"(addr));
}
__device__ __forceinline__ void ldsm_x4_t(uint32_t addr, uint32_t& r0, uint32_t& r1, uint32_t& r2, uint32_t& r3) {
    asm volatile("ldmatrix.sync.aligned.m8n8.x4.trans.shared.b16 {%0,%1,%2,%3}, [%4];"
                 : "=r"(r0), "=r"(r1), "=r"(r2), "=r"(r3) : "r"(addr));
}
__device__ __forceinline__ void mma_bf16(float* c, const uint32_t* a, const uint32_t* b) {
    asm volatile("mma.sync.aligned.m16n8k16.row.col.f32.bf16.bf16.f32 "
                 "{%0,%1,%2,%3},{%4,%5,%6,%7},{%8,%9},{%0,%1,%2,%3};"
                 : "+f"(c[0]), "+f"(c[1]), "+f"(c[2]), "+f"(c[3])
                 : "r"(a[0]), "r"(a[1]), "r"(a[2]), "r"(a[3]), "r"(b[0]), "r"(b[1]));
}

// ---------------- weight conversion (all 7 in one launch) ----------------
struct CvtArgs { const float* s[7]; bf16* d[7]; };
__global__ void cvt_all_kernel(CvtArgs a) {
    int seg = blockIdx.x >> 6;            // 64 blocks per 65536-elem matrix
    int i = ((blockIdx.x & 63) * 256 + threadIdx.x) * 4;
    const float* s = a.s[seg];
    bf16* d = a.d[seg];
    float4 v = *(const float4*)(s + i);
    d[i+0] = __float2bfloat16_rn(v.x);
    d[i+1] = __float2bfloat16_rn(v.y);
    d[i+2] = __float2bfloat16_rn(v.z);
    d[i+3] = __float2bfloat16_rn(v.w);
}

// ---------------- prep ----------------
__global__ void prep_kernel(const float* __restrict__ x, float* __restrict__ pos_out) {
    int r = blockIdx.x;
    const float* xr = x + (size_t)r * (3 + DIM);
    int t = threadIdx.x;
    __shared__ float red[256];
    if (t < 3) pos_out[r*3 + t] = xr[t];
    float f = xr[3 + t];
    g_feat[(size_t)r*DIM + t] = f;
    bf16 hi = __float2bfloat16_rn(f);
    g_fhi[(size_t)r*DIM + t] = hi;
    g_flo[(size_t)r*DIM + t] = __float2bfloat16_rn(f - __bfloat162float(hi));
    red[t] = f * f;
    __syncthreads();
    for (int s = 128; s > 0; s >>= 1) {
        if (t < s) red[t] += red[t + s];
        __syncthreads();
    }
    if (t == 0) g_sq[r] = red[0];
}

// ---------------- bf16 tensor-core GEMM: C[Mx256] = A[Mx256] @ W[256x256] ----------------
template<bool HAS_BIAS, bool HAS_ADD, bool OUT_BF16>
__global__ void __launch_bounds__(256)
mma_gemm(const bf16* __restrict__ Ag, const bf16* __restrict__ Wg,
         const float* __restrict__ bias, const float* __restrict__ addsrc,
         void* __restrict__ Cout) {
    __shared__ bf16 As[128][40];
    __shared__ bf16 Ws_[32][136];
    int t = threadIdx.x;
    int lane = t & 31, w = t >> 5;
    int wm = w & 3, wn = w >> 2;
    int m0 = blockIdx.x * 128;
    int n0 = blockIdx.y * 128;

    float acc[2][8][4];
#pragma unroll
    for (int mi = 0; mi < 2; mi++)
#pragma unroll
        for (int nj = 0; nj < 8; nj++)
#pragma unroll
            for (int e = 0; e < 4; e++) acc[mi][nj][e] = 0.f;

    for (int kb = 0; kb < 256; kb += 32) {
#pragma unroll
        for (int q = 0; q < 2; q++) {
            int flat = t * 2 + q;
            int row = flat >> 2, col = (flat & 3) * 8;
            *(uint4*)&As[row][col] = *(const uint4*)(Ag + ((size_t)(m0 + row) * 256 + kb + col));
        }
#pragma unroll
        for (int q = 0; q < 2; q++) {
            int flat = t * 2 + q;
            int row = flat >> 4, col = (flat & 15) * 8;
            *(uint4*)&Ws_[row][col] = *(const uint4*)(Wg + ((size_t)(kb + row) * 256 + n0 + col));
        }
        __syncthreads();
#pragma unroll
        for (int kk = 0; kk < 32; kk += 16) {
            uint32_t a[2][4], bfr[8][2];
#pragma unroll
            for (int mi = 0; mi < 2; mi++) {
                uint32_t addr = smem_u32(&As[wm*32 + mi*16 + (lane & 15)][kk + (lane >> 4) * 8]);
                ldsm_x4(addr, a[mi][0], a[mi][1], a[mi][2], a[mi][3]);
            }
#pragma unroll
            for (int g = 0; g < 4; g++) {
                uint32_t r0, r1, r2, r3;
                uint32_t addr = smem_u32(&Ws_[kk + (lane & 15)][wn*64 + g*16 + (lane >> 4) * 8]);
                ldsm_x4_t(addr, r0, r1, r2, r3);
                bfr[g*2][0] = r0; bfr[g*2][1] = r1;
                bfr[g*2+1][0] = r2; bfr[g*2+1][1] = r3;
            }
#pragma unroll
            for (int mi = 0; mi < 2; mi++)
#pragma unroll
                for (int nj = 0; nj < 8; nj++)
                    mma_bf16(acc[mi][nj], a[mi], bfr[nj]);
        }
        __syncthreads();
    }

#pragma unroll
    for (int mi = 0; mi < 2; mi++) {
#pragma unroll
        for (int nj = 0; nj < 8; nj++) {
            int r = m0 + wm*32 + mi*16 + (lane >> 2);
            int cc = n0 + wn*64 + nj*8 + (lane & 3) * 2;
            float v0 = acc[mi][nj][0], v1 = acc[mi][nj][1];
            float v2 = acc[mi][nj][2], v3 = acc[mi][nj][3];
            if (HAS_BIAS) {
                float b0 = bias[cc], b1 = bias[cc+1];
                v0 += b0; v1 += b1; v2 += b0; v3 += b1;
            }
            if (HAS_ADD) {
                v0 += addsrc[(size_t)r*256 + cc];     v1 += addsrc[(size_t)r*256 + cc + 1];
                v2 += addsrc[(size_t)(r+8)*256 + cc]; v3 += addsrc[(size_t)(r+8)*256 + cc + 1];
            }
            if (OUT_BF16) {
                bf16* C = (bf16*)Cout;
                __nv_bfloat162 o0, o1;
                o0.x = __float2bfloat16_rn(v0); o0.y = __float2bfloat16_rn(v1);
                o1.x = __float2bfloat16_rn(v2); o1.y = __float2bfloat16_rn(v3);
                *(__nv_bfloat162*)(C + (size_t)r*256 + cc) = o0;
                *(__nv_bfloat162*)(C + (size_t)(r+8)*256 + cc) = o1;
            } else {
                float* C = (float*)Cout;
                float2 o0 = {v0, v1}, o1 = {v2, v3};
                *(float2*)(C + (size_t)r*256 + cc) = o0;
                *(float2*)(C + (size_t)(r+8)*256 + cc) = o1;
            }
        }
    }
}

// ---------------- distance via split-bf16 tensor cores (unchanged) ----------------
__global__ void __launch_bounds__(256)
dist_mma_kernel() {
    __shared__ union {
        struct { bf16 ah[128][40], al[128][40], bh[128][40], bl[128][40]; } t;
        float ts[64][132];
    } sm;

    int b = blockIdx.y;
    const bf16* FH = g_fhi + (size_t)b * SEQ * DIM;
    const bf16* FL = g_flo + (size_t)b * SEQ * DIM;
    const float* sqb = g_sq + (size_t)b * SEQ;
    float* Dmat = g_dist + (size_t)b * SEQ * SEQ;

    int pid = blockIdx.x;
    int ti = 0;
    while (pid >= 32 - ti) { pid -= 32 - ti; ti++; }
    int tj = ti + pid;
    int i0 = ti * 128, j0 = tj * 128;

    int t = threadIdx.x;
    int lane = t & 31, w = t >> 5;
    int wm = w & 3, wn = w >> 2;

    float acc[2][8][4];
#pragma unroll
    for (int mi = 0; mi < 2; mi++)
#pragma unroll
        for (int nj = 0; nj < 8; nj++)
#pragma unroll
            for (int e = 0; e < 4; e++) acc[mi][nj][e] = 0.f;

    for (int kb = 0; kb < 256; kb += 32) {
#pragma unroll
        for (int q = 0; q < 2; q++) {
            int flat = t * 2 + q;
            int row = flat >> 2, col = (flat & 3) * 8;
            size_t offA = (size_t)(i0 + row) * 256 + kb + col;
            size_t offB = (size_t)(j0 + row) * 256 + kb + col;
            *(uint4*)&sm.t.ah[row][col] = *(const uint4*)(FH + offA);
            *(uint4*)&sm.t.al[row][col] = *(const uint4*)(FL + offA);
            *(uint4*)&sm.t.bh[row][col] = *(const uint4*)(FH + offB);
            *(uint4*)&sm.t.bl[row][col] = *(const uint4*)(FL + offB);
        }
        __syncthreads();
#pragma unroll
        for (int kk = 0; kk < 32; kk += 16) {
            uint32_t ah[2][4], al[2][4], bh[8][2], bl[8][2];
#pragma unroll
            for (int mi = 0; mi < 2; mi++) {
                uint32_t addr = smem_u32(&sm.t.ah[wm*32 + mi*16 + (lane & 15)][kk + (lane >> 4) * 8]);
                ldsm_x4(addr, ah[mi][0], ah[mi][1], ah[mi][2], ah[mi][3]);
                addr = smem_u32(&sm.t.al[wm*32 + mi*16 + (lane & 15)][kk + (lane >> 4) * 8]);
                ldsm_x4(addr, al[mi][0], al[mi][1], al[mi][2], al[mi][3]);
            }
#pragma unroll
            for (int g = 0; g < 4; g++) {
                int nrow = wn*64 + g*16 + (lane & 7) + ((lane >> 4) << 3);
                int ncol = kk + ((lane >> 3) & 1) * 8;
                uint32_t r0, r1, r2, r3;
                ldsm_x4(smem_u32(&sm.t.bh[nrow][ncol]), r0, r1, r2, r3);
                bh[g*2][0] = r0; bh[g*2][1] = r1; bh[g*2+1][0] = r2; bh[g*2+1][1] = r3;
                ldsm_x4(smem_u32(&sm.t.bl[nrow][ncol]), r0, r1, r2, r3);
                bl[g*2][0] = r0; bl[g*2][1] = r1; bl[g*2+1][0] = r2; bl[g*2+1][1] = r3;
            }
#pragma unroll
            for (int mi = 0; mi < 2; mi++)
#pragma unroll
                for (int nj = 0; nj < 8; nj++) {
                    mma_bf16(acc[mi][nj], ah[mi], bh[nj]);
                    mma_bf16(acc[mi][nj], ah[mi], bl[nj]);
                    mma_bf16(acc[mi][nj], al[mi], bh[nj]);
                }
        }
        __syncthreads();
    }

#pragma unroll
    for (int mi = 0; mi < 2; mi++) {
        int r = i0 + wm*32 + mi*16 + (lane >> 2);
        float si0 = sqb[r], si1 = sqb[r + 8];
#pragma unroll
        for (int nj = 0; nj < 8; nj++) {
            int cc = j0 + wn*64 + nj*8 + (lane & 3) * 2;
            float sj0 = sqb[cc], sj1 = sqb[cc + 1];
            float d0 = si0 + sj0 - 2.f * acc[mi][nj][0];
            float d1 = si0 + sj1 - 2.f * acc[mi][nj][1];
            float d2 = si1 + sj0 - 2.f * acc[mi][nj][2];
            float d3 = si1 + sj1 - 2.f * acc[mi][nj][3];
            acc[mi][nj][0] = d0; acc[mi][nj][1] = d1;
            acc[mi][nj][2] = d2; acc[mi][nj][3] = d3;
            float2 o0 = {d0, d1}, o1 = {d2, d3};
            *(float2*)(Dmat + (size_t)r * SEQ + cc) = o0;
            *(float2*)(Dmat + (size_t)(r + 8) * SEQ + cc) = o1;
        }
    }
    if (ti != tj) {
        __syncthreads();
#pragma unroll
        for (int p = 0; p < 2; p++) {
            if (wn == p) {
#pragma unroll
                for (int mi = 0; mi < 2; mi++) {
                    int lm = wm*32 + mi*16 + (lane >> 2);
#pragma unroll
                    for (int nj = 0; nj < 8; nj++) {
                        int ln = nj*8 + (lane & 3) * 2;
                        sm.ts[ln][lm]       = acc[mi][nj][0];
                        sm.ts[ln+1][lm]     = acc[mi][nj][1];
                        sm.ts[ln][lm+8]     = acc[mi][nj][2];
                        sm.ts[ln+1][lm+8]   = acc[mi][nj][3];
                    }
                }
            }
            __syncthreads();
#pragma unroll
            for (int qq = 0; qq < 8; qq++) {
                int flat = t + qq * 256;
                int rj = flat >> 5;
                int c4 = (flat & 31) * 4;
                float4 v = *(float4*)&sm.ts[rj][c4];
                *(float4*)(Dmat + (size_t)(j0 + p*64 + rj) * SEQ + i0 + c4) = v;
            }
            __syncthreads();
        }
    }
}

// ---------------- top-K ----------------
__global__ void __launch_bounds__(128)
topk_kernel() {
    __shared__ float sv[4][512];
    __shared__ int   si[4][512];
    int w = threadIdx.x >> 5, lane = threadIdx.x & 31;
    int r = blockIdx.x * 4 + w;
    int b = r >> 12, i = r & (SEQ - 1);
    const float* row = g_dist + ((size_t)b*SEQ + i)*SEQ;

    float v[16]; int id[16];
#pragma unroll
    for (int t = 0; t < 16; t++) { v[t] = CUDART_INF_F; id[t] = -1; }

    for (int j = lane; j < SEQ; j += 32) {
        float d = row[j];
        if (d < v[15]) {
            float cv = d; int ci = j;
#pragma unroll
            for (int t = 0; t < 16; t++) {
                if (cv < v[t]) {
                    float tv = v[t]; v[t] = cv; cv = tv;
                    int ti2 = id[t]; id[t] = ci; ci = ti2;
                }
            }
        }
    }
#pragma unroll
    for (int t = 0; t < 16; t++) { sv[w][lane*16 + t] = v[t]; si[w][lane*16 + t] = id[t]; }
    __syncwarp();

    int p = 0;
    for (int it = 0; it < 16; ++it) {
        float cand = (p < 16) ? sv[w][lane*16 + p] : CUDART_INF_F;
        float bv = cand; int bl = lane;
#pragma unroll
        for (int off = 16; off; off >>= 1) {
            float ov = __shfl_xor_sync(0xffffffffu, bv, off);
            int   ol = __shfl_xor_sync(0xffffffffu, bl, off);
            if (ov < bv || (ov == bv && ol < bl)) { bv = ov; bl = ol; }
        }
        if (lane == bl) {
            g_idx[r*16 + it] = b*SEQ + si[w][lane*16 + p];
            p++;
        }
    }
}

// ---------------- fused attention: R-build + R@g2 + softmax + v-contraction ----------------
// Block: 8 points x 16 neighbors = 128 M-rows, 256 N-cols. 512 threads, 16 warps (4m x 4n).
// g2_b dropped: per-column constant cancels in softmax over neighbors.
__global__ void __launch_bounds__(512, 1)
attn_fused_kernel() {
    __shared__ bf16 Rs[128][40];
    __shared__ bf16 Ws_[32][264];
    __shared__ int  nbr[128];

    int t = threadIdx.x;
    int lane = t & 31, w = t >> 5;
    int wm = w & 3, wn = w >> 2;
    int m0 = blockIdx.x * 128;    // row into (point, neighbor) space

    if (t < 128) nbr[t] = g_idx[m0 + t];
    __syncthreads();

    float acc[2][8][4];
#pragma unroll
    for (int mi = 0; mi < 2; mi++)
#pragma unroll
        for (int nj = 0; nj < 8; nj++)
#pragma unroll
            for (int e = 0; e < 4; e++) acc[mi][nj][e] = 0.f;

    // per-thread R-build assignment: 8 bf16 (one uint4) of one row per chunk
    int rrow = t >> 2;
    int cg = (t & 3) * 8;
    int pt_r = (m0 + rrow) >> 4;
    int nr_r = nbr[rrow];
    const uint4* qrow = (const uint4*)(g_qgb  + (size_t)pt_r * 256);
    const uint4* krow = (const uint4*)(g_kg1b + (size_t)nr_r * 256);
    __nv_bfloat162 z2 = __float2bfloat162_rn(0.f);

    for (int kb = 0; kb < 256; kb += 32) {
        // build R chunk [128][32]
        {
            uint4 qv = qrow[(kb + cg) >> 3];
            uint4 kv = krow[(kb + cg) >> 3];
            const __nv_bfloat162* qp = (const __nv_bfloat162*)&qv;
            const __nv_bfloat162* kp = (const __nv_bfloat162*)&kv;
            uint4 ov;
            __nv_bfloat162* op = (__nv_bfloat162*)&ov;
#pragma unroll
            for (int e = 0; e < 4; e++)
                op[e] = __hmax2(__hsub2(qp[e], kp[e]), z2);
            *(uint4*)&Rs[rrow][cg] = ov;
        }
        // load g2 chunk [32][256]
#pragma unroll
        for (int q = 0; q < 2; q++) {
            int flat = t * 2 + q;
            int row = flat >> 5, col = (flat & 31) * 8;
            *(uint4*)&Ws_[row][col] = *(const uint4*)(g_g2b + (size_t)(kb + row) * 256 + col);
        }
        __syncthreads();
#pragma unroll
        for (int kk = 0; kk < 32; kk += 16) {
            uint32_t a[2][4], bfr[8][2];
#pragma unroll
            for (int mi = 0; mi < 2; mi++) {
                uint32_t addr = smem_u32(&Rs[wm*32 + mi*16 + (lane & 15)][kk + (lane >> 4) * 8]);
                ldsm_x4(addr, a[mi][0], a[mi][1], a[mi][2], a[mi][3]);
            }
#pragma unroll
            for (int g = 0; g < 4; g++) {
                uint32_t r0, r1, r2, r3;
                uint32_t addr = smem_u32(&Ws_[kk + (lane & 15)][wn*64 + g*16 + (lane >> 4) * 8]);
                ldsm_x4_t(addr, r0, r1, r2, r3);
                bfr[g*2][0] = r0; bfr[g*2][1] = r1;
                bfr[g*2+1][0] = r2; bfr[g*2+1][1] = r3;
            }
#pragma unroll
            for (int mi = 0; mi < 2; mi++)
#pragma unroll
                for (int nj = 0; nj < 8; nj++)
                    mma_bf16(acc[mi][nj], a[mi], bfr[nj]);
        }
        __syncthreads();
    }

    // epilogue: softmax over the 16 rows of each m16 fragment (one point) + v-contraction
    const float inv = 0.0625f;   // 1/sqrt(256)
#pragma unroll
    for (int mi = 0; mi < 2; mi++) {
        int lrow = wm * 32 + mi * 16;
        int ptm = (m0 + lrow) >> 4;
        int nrA = nbr[lrow + (lane >> 2)];
        int nrB = nbr[lrow + 8 + (lane >> 2)];
#pragma unroll
        for (int nj = 0; nj < 8; nj++) {
            int cc = wn * 64 + nj * 8 + (lane & 3) * 2;
            float x0 = acc[mi][nj][0], x1 = acc[mi][nj][1];
            float x2 = acc[mi][nj][2], x3 = acc[mi][nj][3];
            // max over 16 rows (this thread's 2 rows + xor 4/8/16 lanes)
            float mA = fmaxf(x0, x2), mB = fmaxf(x1, x3);
#pragma unroll
            for (int off = 4; off <= 16; off <<= 1) {
                mA = fmaxf(mA, __shfl_xor_sync(0xffffffffu, mA, off));
                mB = fmaxf(mB, __shfl_xor_sync(0xffffffffu, mB, off));
            }
            float e0 = __expf((x0 - mA) * inv), e2 = __expf((x2 - mA) * inv);
            float e1 = __expf((x1 - mB) * inv), e3 = __expf((x3 - mB) * inv);
            __nv_bfloat162 vA = *(const __nv_bfloat162*)(g_vf + (size_t)nrA * 256 + cc);
            __nv_bfloat162 vB = *(const __nv_bfloat162*)(g_vf + (size_t)nrB * 256 + cc);
            float sA = e0 + e2, sB = e1 + e3;
            float wA = e0 * __bfloat162float(vA.x) + e2 * __bfloat162float(vB.x);
            float wB = e1 * __bfloat162float(vA.y) + e3 * __bfloat162float(vB.y);
#pragma unroll
            for (int off = 4; off <= 16; off <<= 1) {
                sA += __shfl_xor_sync(0xffffffffu, sA, off);
                sB += __shfl_xor_sync(0xffffffffu, sB, off);
                wA += __shfl_xor_sync(0xffffffffu, wA, off);
                wB += __shfl_xor_sync(0xffffffffu, wB, off);
            }
            if ((lane >> 2) == 0) {
                __nv_bfloat162 o;
                o.x = __float2bfloat16_rn(wA / sA);
                o.y = __float2bfloat16_rn(wB / sB);
                *(__nv_bfloat162*)(g_resb + (size_t)ptm * 256 + cc) = o;
            }
        }
    }
}

// ---------------- launch ----------------
extern "C" void kernel_launch(void* const* d_in, const int* in_sizes, int n_in,
                              void* d_out, int out_size) {
    const float* x     = (const float*)d_in[0];
    const float* fc1_w = (const float*)d_in[1];
    const float* fc1_b = (const float*)d_in[2];
    const float* fc2_w = (const float*)d_in[3];
    const float* fc2_b = (const float*)d_in[4];
    const float* wq_w  = (const float*)d_in[5];
    const float* wk_w  = (const float*)d_in[6];
    const float* wv_w  = (const float*)d_in[7];
    const float* g1_w  = (const float*)d_in[8];
    const float* g1_b  = (const float*)d_in[9];
    const float* g2_w  = (const float*)d_in[10];
    const float* g2_b  = (const float*)d_in[11];  (void)g2_b;
    float* out = (float*)d_out;

    bf16 *p_fc1b, *p_wqb, *p_wkb, *p_wvb, *p_g1b, *p_g2b, *p_fc2b, *p_wq1, *p_wk1;
    bf16 *p_fhi, *p_h, *p_vf, *p_qgb, *p_kg1b, *p_resb;
    float *p_feat;
    cudaGetSymbolAddress((void**)&p_fc1b, g_fc1b);
    cudaGetSymbolAddress((void**)&p_wqb,  g_wqb);
    cudaGetSymbolAddress((void**)&p_wkb,  g_wkb);
    cudaGetSymbolAddress((void**)&p_wvb,  g_wvb);
    cudaGetSymbolAddress((void**)&p_g1b,  g_g1b);
    cudaGetSymbolAddress((void**)&p_g2b,  g_g2b);
    cudaGetSymbolAddress((void**)&p_fc2b, g_fc2b);
    cudaGetSymbolAddress((void**)&p_wq1,  g_wq1);
    cudaGetSymbolAddress((void**)&p_wk1,  g_wk1);
    cudaGetSymbolAddress((void**)&p_fhi,  g_fhi);
    cudaGetSymbolAddress((void**)&p_h,    g_h);
    cudaGetSymbolAddress((void**)&p_vf,   g_vf);
    cudaGetSymbolAddress((void**)&p_qgb,  g_qgb);
    cudaGetSymbolAddress((void**)&p_kg1b, g_kg1b);
    cudaGetSymbolAddress((void**)&p_resb, g_resb);
    cudaGetSymbolAddress((void**)&p_feat, g_feat);

    // all 7 weight conversions in one launch
    CvtArgs ca;
    ca.s[0] = fc1_w; ca.d[0] = p_fc1b;
    ca.s[1] = wq_w;  ca.d[1] = p_wqb;
    ca.s[2] = wk_w;  ca.d[2] = p_wkb;
    ca.s[3] = wv_w;  ca.d[3] = p_wvb;
    ca.s[4] = g1_w;  ca.d[4] = p_g1b;
    ca.s[5] = g2_w;  ca.d[5] = p_g2b;
    ca.s[6] = fc2_w; ca.d[6] = p_fc2b;
    cvt_all_kernel<<<7*64, 256>>>(ca);

    prep_kernel<<<NPTS, 256>>>(x, out);

    // composed weights: Wq1 = wq@g1, Wk1 = wk@g1
    mma_gemm<false, false, true><<<dim3(2, 2), 256>>>(p_wqb, p_g1b, nullptr, nullptr, p_wq1);
    mma_gemm<false, false, true><<<dim3(2, 2), 256>>>(p_wkb, p_g1b, nullptr, nullptr, p_wk1);

    // distance + topk
    dist_mma_kernel<<<dim3(528, BATCH), 256>>>();
    topk_kernel<<<NPTS/4, 128>>>();

    // h = feat@fc1 + b ; vf = h@wv ; qg = h@Wq1 + g1_b ; kg1 = h@Wk1
    mma_gemm<true,  false, true><<<dim3(NPTS/128, 2), 256>>>(p_fhi, p_fc1b, fc1_b, nullptr, p_h);
    mma_gemm<false, false, true><<<dim3(NPTS/128, 2), 256>>>(p_h, p_wvb, nullptr, nullptr, p_vf);
    mma_gemm<true,  false, true><<<dim3(NPTS/128, 2), 256>>>(p_h, p_wq1, g1_b, nullptr, p_qgb);
    mma_gemm<false, false, true><<<dim3(NPTS/128, 2), 256>>>(p_h, p_wk1, nullptr, nullptr, p_kg1b);

    // fused: R-build + R@g2 + softmax + v-contraction  (g2_b cancels in softmax)
    attn_fused_kernel<<<(NPTS*KNN)/128, 512>>>();

    // out = res@fc2 + fc2_b + feat
    mma_gemm<true, true, false><<<dim3(NPTS/128, 2), 256>>>(p_resb, p_fc2b, fc2_b, p_feat, out + (size_t)NPTS*3);
}

// round 11
// speedup vs baseline: 4.6326x; 1.1248x over previous
#include <cuda_runtime.h>
#include <cuda_bf16.h>
#include <cuda_fp16.h>
#include <math_constants.h>
#include <math.h>
#include <stdint.h>

#define BATCH 4
#define SEQ   4096
#define NPTS  (BATCH*SEQ)   // 16384
#define DIM   256
#define KNN   16

typedef __nv_bfloat16 bf16;

// ---------------- scratch ----------------
__device__ float g_feat[NPTS*DIM];
__device__ bf16  g_fhi[NPTS*DIM];      // bf16 feat (GEMM input)
__device__ __half g_f16[NPTS*DIM];     // fp16 feat (distance)
__device__ float g_sq[NPTS];
__device__ int   g_idx[NPTS*KNN];
__device__ bf16  g_h  [NPTS*DIM];
__device__ bf16  g_vf [NPTS*DIM];
__device__ bf16  g_qgb [NPTS*DIM];
__device__ bf16  g_kg1b[NPTS*DIM];
__device__ bf16  g_resb[NPTS*DIM];
// bf16 weights
__device__ bf16 g_fc1b[DIM*DIM], g_wqb[DIM*DIM], g_wkb[DIM*DIM], g_wvb[DIM*DIM];
__device__ bf16 g_g1b[DIM*DIM], g_g2b[DIM*DIM], g_fc2b[DIM*DIM];
__device__ bf16 g_wq1[DIM*DIM], g_wk1[DIM*DIM];   // composed wq@g1, wk@g1

// ---------------- helpers ----------------
__device__ __forceinline__ uint32_t smem_u32(const void* p) {
    return (uint32_t)__cvta_generic_to_shared(p);
}
__device__ __forceinline__ void ldsm_x4(uint32_t addr, uint32_t& r0, uint32_t& r1, uint32_t& r2, uint32_t& r3) {
    asm volatile("ldmatrix.sync.aligned.m8n8.x4.shared.b16 {%0,%1,%2,%3}, [%4];"
                 : "=r"(r0), "=r"(r1), "=r"(r2), "=r"(r3) : "r"(addr));
}
__device__ __forceinline__ void ldsm_x4_t(uint32_t addr, uint32_t& r0, uint32_t& r1, uint32_t& r2, uint32_t& r3) {
    asm volatile("ldmatrix.sync.aligned.m8n8.x4.trans.shared.b16 {%0,%1,%2,%3}, [%4];"
                 : "=r"(r0), "=r"(r1), "=r"(r2), "=r"(r3) : "r"(addr));
}
__device__ __forceinline__ void mma_bf16(float* c, const uint32_t* a, const uint32_t* b) {
    asm volatile("mma.sync.aligned.m16n8k16.row.col.f32.bf16.bf16.f32 "
                 "{%0,%1,%2,%3},{%4,%5,%6,%7},{%8,%9},{%0,%1,%2,%3};"
                 : "+f"(c[0]), "+f"(c[1]), "+f"(c[2]), "+f"(c[3])
                 : "r"(a[0]), "r"(a[1]), "r"(a[2]), "r"(a[3]), "r"(b[0]), "r"(b[1]));
}
__device__ __forceinline__ void mma_fp16(float* c, const uint32_t* a, const uint32_t* b) {
    asm volatile("mma.sync.aligned.m16n8k16.row.col.f32.f16.f16.f32 "
                 "{%0,%1,%2,%3},{%4,%5,%6,%7},{%8,%9},{%0,%1,%2,%3};"
                 : "+f"(c[0]), "+f"(c[1]), "+f"(c[2]), "+f"(c[3])
                 : "r"(a[0]), "r"(a[1]), "r"(a[2]), "r"(a[3]), "r"(b[0]), "r"(b[1]));
}

// ---------------- weight conversion (all 7 in one launch) ----------------
struct CvtArgs { const float* s[7]; bf16* d[7]; };
__global__ void cvt_all_kernel(CvtArgs a) {
    int seg = blockIdx.x >> 6;
    int i = ((blockIdx.x & 63) * 256 + threadIdx.x) * 4;
    const float* s = a.s[seg];
    bf16* d = a.d[seg];
    float4 v = *(const float4*)(s + i);
    d[i+0] = __float2bfloat16_rn(v.x);
    d[i+1] = __float2bfloat16_rn(v.y);
    d[i+2] = __float2bfloat16_rn(v.z);
    d[i+3] = __float2bfloat16_rn(v.w);
}

// ---------------- prep ----------------
__global__ void prep_kernel(const float* __restrict__ x, float* __restrict__ pos_out) {
    int r = blockIdx.x;
    const float* xr = x + (size_t)r * (3 + DIM);
    int t = threadIdx.x;
    __shared__ float red[256];
    if (t < 3) pos_out[r*3 + t] = xr[t];
    float f = xr[3 + t];
    g_feat[(size_t)r*DIM + t] = f;
    g_fhi[(size_t)r*DIM + t] = __float2bfloat16_rn(f);
    g_f16[(size_t)r*DIM + t] = __float2half_rn(f);
    red[t] = f * f;
    __syncthreads();
    for (int s = 128; s > 0; s >>= 1) {
        if (t < s) red[t] += red[t + s];
        __syncthreads();
    }
    if (t == 0) g_sq[r] = red[0];
}

// ================= fused distance (fp16 mma.sync) + top-K =================
// Grid (32, BATCH), 256 threads. Block owns 128 i-rows; A strip resident in SMEM;
// streams 32 j-tiles (128 wide). Key = sq_j - 2*dot (sq_i per-row const drops out).
// Per tile: fragments -> padded smem tile; 2 threads/row scan into in-register
// top-16; final 2-way merge per row. No dist matrix, no separate topk kernel.
#define DT_AS_OFF   0
#define DT_AS_LD    264                        // halfwords per A row
#define DT_AS_SZ    (128*DT_AS_LD*2)           // 67584
#define DT_BS_OFF   DT_AS_SZ
#define DT_BS_LD    40
#define DT_BS_SZ    (128*DT_BS_LD*2)           // 10240
#define DT_SQ_OFF   (DT_BS_OFF + DT_BS_SZ)     // 77824
#define DT_SD_OFF   (DT_SQ_OFF + 512)          // 78336
#define DT_SD_LD    129                        // floats per sd row
#define DT_SMEM_SZ  (DT_SD_OFF + 128*DT_SD_LD*4)  // 144384

__global__ void __launch_bounds__(256, 1)
dist_topk_kernel() {
    extern __shared__ char smem[];
    __half* As = (__half*)(smem + DT_AS_OFF);
    __half* Bs = (__half*)(smem + DT_BS_OFF);
    float* sq_s = (float*)(smem + DT_SQ_OFF);
    float* sd   = (float*)(smem + DT_SD_OFF);

    int t = threadIdx.x;
    int lane = t & 31, w = t >> 5;
    int wm = w & 3, wn = w >> 2;
    int b = blockIdx.y;
    int i0 = blockIdx.x * 128;

    const __half* F = g_f16 + (size_t)b * SEQ * DIM;
    const float* sqb = g_sq + (size_t)b * SEQ;

    // resident A strip: 128 x 256 fp16
    for (int idx = t; idx < 128 * 32; idx += 256) {
        int r = idx >> 5, c = (idx & 31) * 8;
        *(uint4*)(As + r * DT_AS_LD + c) = *(const uint4*)(F + (size_t)(i0 + r) * 256 + c);
    }

    // per-thread running top-16 for row (t>>1), half (t&1)
    float tv[16]; int ti_[16];
#pragma unroll
    for (int n = 0; n < 16; n++) { tv[n] = CUDART_INF_F; ti_[n] = -1; }
    int srow = t >> 1, shalf = t & 1;
    const float* rowp = sd + srow * DT_SD_LD + shalf * 64;

    for (int jt = 0; jt < 32; jt++) {
        int j0 = jt * 128;
        if (t < 128) sq_s[t] = sqb[j0 + t];

        float acc[2][8][4];
#pragma unroll
        for (int mi = 0; mi < 2; mi++)
#pragma unroll
            for (int nj = 0; nj < 8; nj++)
#pragma unroll
                for (int e = 0; e < 4; e++) acc[mi][nj][e] = 0.f;

        for (int kb = 0; kb < 256; kb += 32) {
#pragma unroll
            for (int q = 0; q < 2; q++) {
                int flat = t * 2 + q;                 // 512 uint4 = 128x32 fp16
                int r = flat >> 2, c = (flat & 3) * 8;
                *(uint4*)(Bs + r * DT_BS_LD + c) = *(const uint4*)(F + (size_t)(j0 + r) * 256 + kb + c);
            }
            __syncthreads();
#pragma unroll
            for (int kk = 0; kk < 32; kk += 16) {
                uint32_t a[2][4], bfr[8][2];
#pragma unroll
                for (int mi = 0; mi < 2; mi++) {
                    uint32_t addr = smem_u32(As + (wm*32 + mi*16 + (lane & 15)) * DT_AS_LD + kb + kk + (lane >> 4) * 8);
                    ldsm_x4(addr, a[mi][0], a[mi][1], a[mi][2], a[mi][3]);
                }
#pragma unroll
                for (int g = 0; g < 4; g++) {
                    int nrow = wn*64 + g*16 + (lane & 7) + ((lane >> 4) << 3);
                    int ncol = kk + ((lane >> 3) & 1) * 8;
                    uint32_t r0, r1, r2, r3;
                    ldsm_x4(smem_u32(Bs + nrow * DT_BS_LD + ncol), r0, r1, r2, r3);
                    bfr[g*2][0] = r0; bfr[g*2][1] = r1;
                    bfr[g*2+1][0] = r2; bfr[g*2+1][1] = r3;
                }
#pragma unroll
                for (int mi = 0; mi < 2; mi++)
#pragma unroll
                    for (int nj = 0; nj < 8; nj++)
                        mma_fp16(acc[mi][nj], a[mi], bfr[nj]);
            }
            __syncthreads();
        }

        // write keys into sd
#pragma unroll
        for (int mi = 0; mi < 2; mi++) {
            int r = wm*32 + mi*16 + (lane >> 2);
#pragma unroll
            for (int nj = 0; nj < 8; nj++) {
                int c = wn*64 + nj*8 + (lane & 3) * 2;
                float s0 = sq_s[c], s1 = sq_s[c + 1];
                sd[r * DT_SD_LD + c]           = s0 - 2.f * acc[mi][nj][0];
                sd[r * DT_SD_LD + c + 1]       = s1 - 2.f * acc[mi][nj][1];
                sd[(r + 8) * DT_SD_LD + c]     = s0 - 2.f * acc[mi][nj][2];
                sd[(r + 8) * DT_SD_LD + c + 1] = s1 - 2.f * acc[mi][nj][3];
            }
        }
        __syncthreads();

        // scan 64 keys of this thread's row-half, maintain top-16
        int jbase = j0 + shalf * 64;
#pragma unroll 4
        for (int j = 0; j < 64; j++) {
            float d = rowp[j];
            if (d < tv[15]) {
                float cv = d; int ci = jbase + j;
#pragma unroll
                for (int n = 0; n < 16; n++) {
                    if (cv < tv[n]) {
                        float tvv = tv[n]; tv[n] = cv; cv = tvv;
                        int tii = ti_[n]; ti_[n] = ci; ci = tii;
                    }
                }
            }
        }
        __syncthreads();
    }

    // merge: both halves' lists via smem (values in sd[row][0..31], ids in [32..63])
#pragma unroll
    for (int n = 0; n < 16; n++) {
        sd[srow * DT_SD_LD + shalf * 16 + n] = tv[n];
        ((int*)sd)[srow * DT_SD_LD + 32 + shalf * 16 + n] = ti_[n];
    }
    __syncthreads();
    if (t < 128) {
        float mv[16]; int mid[16];
#pragma unroll
        for (int n = 0; n < 16; n++) { mv[n] = CUDART_INF_F; mid[n] = -1; }
#pragma unroll
        for (int p = 0; p < 32; p++) {
            float d = sd[t * DT_SD_LD + p];
            if (d < mv[15]) {
                float cv = d; int ci = ((int*)sd)[t * DT_SD_LD + 32 + p];
#pragma unroll
                for (int n = 0; n < 16; n++) {
                    if (cv < mv[n]) {
                        float tvv = mv[n]; mv[n] = cv; cv = tvv;
                        int tii = mid[n]; mid[n] = ci; ci = tii;
                    }
                }
            }
        }
        size_t base = ((size_t)b * SEQ + i0 + t) * 16;
#pragma unroll
        for (int n = 0; n < 16; n++) g_idx[base + n] = b * SEQ + mid[n];
    }
}

// ---------------- bf16 tensor-core GEMM: C[Mx256] = A[Mx256] @ W[256x256] ----------------
template<bool HAS_BIAS, bool HAS_ADD, bool OUT_BF16>
__global__ void __launch_bounds__(256)
mma_gemm(const bf16* __restrict__ Ag, const bf16* __restrict__ Wg,
         const float* __restrict__ bias, const float* __restrict__ addsrc,
         void* __restrict__ Cout) {
    __shared__ bf16 As[128][40];
    __shared__ bf16 Ws_[32][136];
    int t = threadIdx.x;
    int lane = t & 31, w = t >> 5;
    int wm = w & 3, wn = w >> 2;
    int m0 = blockIdx.x * 128;
    int n0 = blockIdx.y * 128;

    float acc[2][8][4];
#pragma unroll
    for (int mi = 0; mi < 2; mi++)
#pragma unroll
        for (int nj = 0; nj < 8; nj++)
#pragma unroll
            for (int e = 0; e < 4; e++) acc[mi][nj][e] = 0.f;

    for (int kb = 0; kb < 256; kb += 32) {
#pragma unroll
        for (int q = 0; q < 2; q++) {
            int flat = t * 2 + q;
            int row = flat >> 2, col = (flat & 3) * 8;
            *(uint4*)&As[row][col] = *(const uint4*)(Ag + ((size_t)(m0 + row) * 256 + kb + col));
        }
#pragma unroll
        for (int q = 0; q < 2; q++) {
            int flat = t * 2 + q;
            int row = flat >> 4, col = (flat & 15) * 8;
            *(uint4*)&Ws_[row][col] = *(const uint4*)(Wg + ((size_t)(kb + row) * 256 + n0 + col));
        }
        __syncthreads();
#pragma unroll
        for (int kk = 0; kk < 32; kk += 16) {
            uint32_t a[2][4], bfr[8][2];
#pragma unroll
            for (int mi = 0; mi < 2; mi++) {
                uint32_t addr = smem_u32(&As[wm*32 + mi*16 + (lane & 15)][kk + (lane >> 4) * 8]);
                ldsm_x4(addr, a[mi][0], a[mi][1], a[mi][2], a[mi][3]);
            }
#pragma unroll
            for (int g = 0; g < 4; g++) {
                uint32_t r0, r1, r2, r3;
                uint32_t addr = smem_u32(&Ws_[kk + (lane & 15)][wn*64 + g*16 + (lane >> 4) * 8]);
                ldsm_x4_t(addr, r0, r1, r2, r3);
                bfr[g*2][0] = r0; bfr[g*2][1] = r1;
                bfr[g*2+1][0] = r2; bfr[g*2+1][1] = r3;
            }
#pragma unroll
            for (int mi = 0; mi < 2; mi++)
#pragma unroll
                for (int nj = 0; nj < 8; nj++)
                    mma_bf16(acc[mi][nj], a[mi], bfr[nj]);
        }
        __syncthreads();
    }

#pragma unroll
    for (int mi = 0; mi < 2; mi++) {
#pragma unroll
        for (int nj = 0; nj < 8; nj++) {
            int r = m0 + wm*32 + mi*16 + (lane >> 2);
            int cc = n0 + wn*64 + nj*8 + (lane & 3) * 2;
            float v0 = acc[mi][nj][0], v1 = acc[mi][nj][1];
            float v2 = acc[mi][nj][2], v3 = acc[mi][nj][3];
            if (HAS_BIAS) {
                float b0 = bias[cc], b1 = bias[cc+1];
                v0 += b0; v1 += b1; v2 += b0; v3 += b1;
            }
            if (HAS_ADD) {
                v0 += addsrc[(size_t)r*256 + cc];     v1 += addsrc[(size_t)r*256 + cc + 1];
                v2 += addsrc[(size_t)(r+8)*256 + cc]; v3 += addsrc[(size_t)(r+8)*256 + cc + 1];
            }
            if (OUT_BF16) {
                bf16* C = (bf16*)Cout;
                __nv_bfloat162 o0, o1;
                o0.x = __float2bfloat16_rn(v0); o0.y = __float2bfloat16_rn(v1);
                o1.x = __float2bfloat16_rn(v2); o1.y = __float2bfloat16_rn(v3);
                *(__nv_bfloat162*)(C + (size_t)r*256 + cc) = o0;
                *(__nv_bfloat162*)(C + (size_t)(r+8)*256 + cc) = o1;
            } else {
                float* C = (float*)Cout;
                float2 o0 = {v0, v1}, o1 = {v2, v3};
                *(float2*)(C + (size_t)r*256 + cc) = o0;
                *(float2*)(C + (size_t)(r+8)*256 + cc) = o1;
            }
        }
    }
}

// ---------------- fused attention: R-build + R@g2 + softmax + v-contraction ----------------
__global__ void __launch_bounds__(512, 1)
attn_fused_kernel() {
    __shared__ bf16 Rs[128][40];
    __shared__ bf16 Ws_[32][264];
    __shared__ int  nbr[128];

    int t = threadIdx.x;
    int lane = t & 31, w = t >> 5;
    int wm = w & 3, wn = w >> 2;
    int m0 = blockIdx.x * 128;

    if (t < 128) nbr[t] = g_idx[m0 + t];
    __syncthreads();

    float acc[2][8][4];
#pragma unroll
    for (int mi = 0; mi < 2; mi++)
#pragma unroll
        for (int nj = 0; nj < 8; nj++)
#pragma unroll
            for (int e = 0; e < 4; e++) acc[mi][nj][e] = 0.f;

    int rrow = t >> 2;
    int cg = (t & 3) * 8;
    int pt_r = (m0 + rrow) >> 4;
    int nr_r = nbr[rrow];
    const uint4* qrow = (const uint4*)(g_qgb  + (size_t)pt_r * 256);
    const uint4* krow = (const uint4*)(g_kg1b + (size_t)nr_r * 256);
    __nv_bfloat162 z2 = __float2bfloat162_rn(0.f);

    for (int kb = 0; kb < 256; kb += 32) {
        {
            uint4 qv = qrow[(kb + cg) >> 3];
            uint4 kv = krow[(kb + cg) >> 3];
            const __nv_bfloat162* qp = (const __nv_bfloat162*)&qv;
            const __nv_bfloat162* kp = (const __nv_bfloat162*)&kv;
            uint4 ov;
            __nv_bfloat162* op = (__nv_bfloat162*)&ov;
#pragma unroll
            for (int e = 0; e < 4; e++)
                op[e] = __hmax2(__hsub2(qp[e], kp[e]), z2);
            *(uint4*)&Rs[rrow][cg] = ov;
        }
#pragma unroll
        for (int q = 0; q < 2; q++) {
            int flat = t * 2 + q;
            int row = flat >> 5, col = (flat & 31) * 8;
            *(uint4*)&Ws_[row][col] = *(const uint4*)(g_g2b + (size_t)(kb + row) * 256 + col);
        }
        __syncthreads();
#pragma unroll
        for (int kk = 0; kk < 32; kk += 16) {
            uint32_t a[2][4], bfr[8][2];
#pragma unroll
            for (int mi = 0; mi < 2; mi++) {
                uint32_t addr = smem_u32(&Rs[wm*32 + mi*16 + (lane & 15)][kk + (lane >> 4) * 8]);
                ldsm_x4(addr, a[mi][0], a[mi][1], a[mi][2], a[mi][3]);
            }
#pragma unroll
            for (int g = 0; g < 4; g++) {
                uint32_t r0, r1, r2, r3;
                uint32_t addr = smem_u32(&Ws_[kk + (lane & 15)][wn*64 + g*16 + (lane >> 4) * 8]);
                ldsm_x4_t(addr, r0, r1, r2, r3);
                bfr[g*2][0] = r0; bfr[g*2][1] = r1;
                bfr[g*2+1][0] = r2; bfr[g*2+1][1] = r3;
            }
#pragma unroll
            for (int mi = 0; mi < 2; mi++)
#pragma unroll
                for (int nj = 0; nj < 8; nj++)
                    mma_bf16(acc[mi][nj], a[mi], bfr[nj]);
        }
        __syncthreads();
    }

    const float inv = 0.0625f;
#pragma unroll
    for (int mi = 0; mi < 2; mi++) {
        int lrow = wm * 32 + mi * 16;
        int ptm = (m0 + lrow) >> 4;
        int nrA = nbr[lrow + (lane >> 2)];
        int nrB = nbr[lrow + 8 + (lane >> 2)];
#pragma unroll
        for (int nj = 0; nj < 8; nj++) {
            int cc = wn * 64 + nj * 8 + (lane & 3) * 2;
            float x0 = acc[mi][nj][0], x1 = acc[mi][nj][1];
            float x2 = acc[mi][nj][2], x3 = acc[mi][nj][3];
            float mA = fmaxf(x0, x2), mB = fmaxf(x1, x3);
#pragma unroll
            for (int off = 4; off <= 16; off <<= 1) {
                mA = fmaxf(mA, __shfl_xor_sync(0xffffffffu, mA, off));
                mB = fmaxf(mB, __shfl_xor_sync(0xffffffffu, mB, off));
            }
            float e0 = __expf((x0 - mA) * inv), e2 = __expf((x2 - mA) * inv);
            float e1 = __expf((x1 - mB) * inv), e3 = __expf((x3 - mB) * inv);
            __nv_bfloat162 vA = *(const __nv_bfloat162*)(g_vf + (size_t)nrA * 256 + cc);
            __nv_bfloat162 vB = *(const __nv_bfloat162*)(g_vf + (size_t)nrB * 256 + cc);
            float sA = e0 + e2, sB = e1 + e3;
            float wA = e0 * __bfloat162float(vA.x) + e2 * __bfloat162float(vB.x);
            float wB = e1 * __bfloat162float(vA.y) + e3 * __bfloat162float(vB.y);
#pragma unroll
            for (int off = 4; off <= 16; off <<= 1) {
                sA += __shfl_xor_sync(0xffffffffu, sA, off);
                sB += __shfl_xor_sync(0xffffffffu, sB, off);
                wA += __shfl_xor_sync(0xffffffffu, wA, off);
                wB += __shfl_xor_sync(0xffffffffu, wB, off);
            }
            if ((lane >> 2) == 0) {
                __nv_bfloat162 o;
                o.x = __float2bfloat16_rn(wA / sA);
                o.y = __float2bfloat16_rn(wB / sB);
                *(__nv_bfloat162*)(g_resb + (size_t)ptm * 256 + cc) = o;
            }
        }
    }
}

// ---------------- launch ----------------
extern "C" void kernel_launch(void* const* d_in, const int* in_sizes, int n_in,
                              void* d_out, int out_size) {
    const float* x     = (const float*)d_in[0];
    const float* fc1_w = (const float*)d_in[1];
    const float* fc1_b = (const float*)d_in[2];
    const float* fc2_w = (const float*)d_in[3];
    const float* fc2_b = (const float*)d_in[4];
    const float* wq_w  = (const float*)d_in[5];
    const float* wk_w  = (const float*)d_in[6];
    const float* wv_w  = (const float*)d_in[7];
    const float* g1_w  = (const float*)d_in[8];
    const float* g1_b  = (const float*)d_in[9];
    const float* g2_w  = (const float*)d_in[10];
    const float* g2_b  = (const float*)d_in[11];  (void)g2_b;
    float* out = (float*)d_out;

    bf16 *p_fc1b, *p_wqb, *p_wkb, *p_wvb, *p_g1b, *p_g2b, *p_fc2b, *p_wq1, *p_wk1;
    bf16 *p_fhi, *p_h, *p_vf, *p_qgb, *p_kg1b, *p_resb;
    float *p_feat;
    cudaGetSymbolAddress((void**)&p_fc1b, g_fc1b);
    cudaGetSymbolAddress((void**)&p_wqb,  g_wqb);
    cudaGetSymbolAddress((void**)&p_wkb,  g_wkb);
    cudaGetSymbolAddress((void**)&p_wvb,  g_wvb);
    cudaGetSymbolAddress((void**)&p_g1b,  g_g1b);
    cudaGetSymbolAddress((void**)&p_g2b,  g_g2b);
    cudaGetSymbolAddress((void**)&p_fc2b, g_fc2b);
    cudaGetSymbolAddress((void**)&p_wq1,  g_wq1);
    cudaGetSymbolAddress((void**)&p_wk1,  g_wk1);
    cudaGetSymbolAddress((void**)&p_fhi,  g_fhi);
    cudaGetSymbolAddress((void**)&p_h,    g_h);
    cudaGetSymbolAddress((void**)&p_vf,   g_vf);
    cudaGetSymbolAddress((void**)&p_qgb,  g_qgb);
    cudaGetSymbolAddress((void**)&p_kg1b, g_kg1b);
    cudaGetSymbolAddress((void**)&p_resb, g_resb);
    cudaGetSymbolAddress((void**)&p_feat, g_feat);

    static int s_attr_done = 0;
    if (!s_attr_done) {
        cudaFuncSetAttribute(dist_topk_kernel,
                             cudaFuncAttributeMaxDynamicSharedMemorySize, DT_SMEM_SZ);
        s_attr_done = 1;
    }

    CvtArgs ca;
    ca.s[0] = fc1_w; ca.d[0] = p_fc1b;
    ca.s[1] = wq_w;  ca.d[1] = p_wqb;
    ca.s[2] = wk_w;  ca.d[2] = p_wkb;
    ca.s[3] = wv_w;  ca.d[3] = p_wvb;
    ca.s[4] = g1_w;  ca.d[4] = p_g1b;
    ca.s[5] = g2_w;  ca.d[5] = p_g2b;
    ca.s[6] = fc2_w; ca.d[6] = p_fc2b;
    cvt_all_kernel<<<7*64, 256>>>(ca);

    prep_kernel<<<NPTS, 256>>>(x, out);

    // fused distance + top-K (fp16 mma.sync, no dist matrix)
    dist_topk_kernel<<<dim3(32, BATCH), 256, DT_SMEM_SZ>>>();

    // composed weights: Wq1 = wq@g1, Wk1 = wk@g1
    mma_gemm<false, false, true><<<dim3(2, 2), 256>>>(p_wqb, p_g1b, nullptr, nullptr, p_wq1);
    mma_gemm<false, false, true><<<dim3(2, 2), 256>>>(p_wkb, p_g1b, nullptr, nullptr, p_wk1);

    // h = feat@fc1 + b ; vf = h@wv ; qg = h@Wq1 + g1_b ; kg1 = h@Wk1
    mma_gemm<true,  false, true><<<dim3(NPTS/128, 2), 256>>>(p_fhi, p_fc1b, fc1_b, nullptr, p_h);
    mma_gemm<false, false, true><<<dim3(NPTS/128, 2), 256>>>(p_h, p_wvb, nullptr, nullptr, p_vf);
    mma_gemm<true,  false, true><<<dim3(NPTS/128, 2), 256>>>(p_h, p_wq1, g1_b, nullptr, p_qgb);
    mma_gemm<false, false, true><<<dim3(NPTS/128, 2), 256>>>(p_h, p_wk1, nullptr, nullptr, p_kg1b);

    // fused attention tail
    attn_fused_kernel<<<(NPTS*KNN)/128, 512>>>();

    // out = res@fc2 + fc2_b + feat
    mma_gemm<true, true, false><<<dim3(NPTS/128, 2), 256>>>(p_resb, p_fc2b, fc2_b, p_feat, out + (size_t)NPTS*3);
}

// round 14
// speedup vs baseline: 5.9993x; 1.2950x over previous
#include <cuda_runtime.h>
#include <cuda_bf16.h>
#include <cuda_fp16.h>
#include <math_constants.h>
#include <math.h>
#include <stdint.h>

#define BATCH 4
#define SEQ   4096
#define NPTS  (BATCH*SEQ)   // 16384
#define DIM   256
#define KNN   16

typedef __nv_bfloat16 bf16;

// ---------------- scratch ----------------
__device__ float g_feat[NPTS*DIM];
__device__ bf16  g_fhi[NPTS*DIM];      // bf16 feat (GEMM input)
__device__ __half g_f16[NPTS*DIM];     // fp16 feat (distance)
__device__ float g_sq[NPTS];
__device__ int   g_idx[NPTS*KNN];
__device__ bf16  g_h  [NPTS*DIM];
__device__ bf16  g_vf [NPTS*DIM];
__device__ bf16  g_qgb [NPTS*DIM];
__device__ bf16  g_kg1b[NPTS*DIM];
__device__ bf16  g_resb[NPTS*DIM];
// bf16 weights
__device__ bf16 g_fc1b[DIM*DIM], g_wqb[DIM*DIM], g_wkb[DIM*DIM], g_wvb[DIM*DIM];
__device__ bf16 g_g1b[DIM*DIM], g_g2b[DIM*DIM], g_fc2b[DIM*DIM];
__device__ bf16 g_wq1[DIM*DIM], g_wk1[DIM*DIM];   // composed wq@g1, wk@g1

// ---------------- helpers ----------------
__device__ __forceinline__ uint32_t smem_u32(const void* p) {
    return (uint32_t)__cvta_generic_to_shared(p);
}
__device__ __forceinline__ void ldsm_x4(uint32_t addr, uint32_t& r0, uint32_t& r1, uint32_t& r2, uint32_t& r3) {
    asm volatile("ldmatrix.sync.aligned.m8n8.x4.shared.b16 {%0,%1,%2,%3}, [%4];"
                 : "=r"(r0), "=r"(r1), "=r"(r2), "=r"(r3) : "r"(addr));
}
__device__ __forceinline__ void ldsm_x4_t(uint32_t addr, uint32_t& r0, uint32_t& r1, uint32_t& r2, uint32_t& r3) {
    asm volatile("ldmatrix.sync.aligned.m8n8.x4.trans.shared.b16 {%0,%1,%2,%3}, [%4];"
                 : "=r"(r0), "=r"(r1), "=r"(r2), "=r"(r3) : "r"(addr));
}
__device__ __forceinline__ void mma_bf16(float* c, const uint32_t* a, const uint32_t* b) {
    asm volatile("mma.sync.aligned.m16n8k16.row.col.f32.bf16.bf16.f32 "
                 "{%0,%1,%2,%3},{%4,%5,%6,%7},{%8,%9},{%0,%1,%2,%3};"
                 : "+f"(c[0]), "+f"(c[1]), "+f"(c[2]), "+f"(c[3])
                 : "r"(a[0]), "r"(a[1]), "r"(a[2]), "r"(a[3]), "r"(b[0]), "r"(b[1]));
}
__device__ __forceinline__ void mma_fp16(float* c, const uint32_t* a, const uint32_t* b) {
    asm volatile("mma.sync.aligned.m16n8k16.row.col.f32.f16.f16.f32 "
                 "{%0,%1,%2,%3},{%4,%5,%6,%7},{%8,%9},{%0,%1,%2,%3};"
                 : "+f"(c[0]), "+f"(c[1]), "+f"(c[2]), "+f"(c[3])
                 : "r"(a[0]), "r"(a[1]), "r"(a[2]), "r"(a[3]), "r"(b[0]), "r"(b[1]));
}

// ---------------- weight conversion (all 7 in one launch) ----------------
struct CvtArgs { const float* s[7]; bf16* d[7]; };
__global__ void cvt_all_kernel(CvtArgs a) {
    int seg = blockIdx.x >> 6;
    int i = ((blockIdx.x & 63) * 256 + threadIdx.x) * 4;
    const float* s = a.s[seg];
    bf16* d = a.d[seg];
    float4 v = *(const float4*)(s + i);
    d[i+0] = __float2bfloat16_rn(v.x);
    d[i+1] = __float2bfloat16_rn(v.y);
    d[i+2] = __float2bfloat16_rn(v.z);
    d[i+3] = __float2bfloat16_rn(v.w);
}

// ---------------- prep ----------------
__global__ void prep_kernel(const float* __restrict__ x, float* __restrict__ pos_out) {
    int r = blockIdx.x;
    const float* xr = x + (size_t)r * (3 + DIM);
    int t = threadIdx.x;
    __shared__ float red[256];
    if (t < 3) pos_out[r*3 + t] = xr[t];
    float f = xr[3 + t];
    g_feat[(size_t)r*DIM + t] = f;
    g_fhi[(size_t)r*DIM + t] = __float2bfloat16_rn(f);
    g_f16[(size_t)r*DIM + t] = __float2half_rn(f);
    red[t] = f * f;
    __syncthreads();
    for (int s = 128; s > 0; s >>= 1) {
        if (t < s) red[t] += red[t + s];
        __syncthreads();
    }
    if (t == 0) g_sq[r] = red[0];
}

// ================= fused distance (fp16 mma.sync) + top-K, full-B-resident =================
// Grid (32, BATCH), 256 threads, ~197 KB smem (1 CTA/SM). Block owns 128 i-rows
// (A resident); per j-tile the FULL 128x256 B tile is staged once -> MMA mainloop
// over K=256 with no internal syncs (2 syncs per tile total).
// Key = sq_j - 2*dot (per-row const sq_i drops out of ordering).
#define DT_LD       264                         // halfwords per A/B row
#define DT_AS_OFF   0
#define DT_AS_SZ    (128*DT_LD*2)               // 67584
#define DT_BS_OFF   DT_AS_SZ
#define DT_BS_SZ    (128*DT_LD*2)               // 67584
#define DT_SQ_OFF   (DT_BS_OFF + DT_BS_SZ)      // 135168
#define DT_SD_OFF   (DT_SQ_OFF + 512)           // 135680
#define DT_SD_LD    129
#define DT_SMEM_SZ  (DT_SD_OFF + 128*DT_SD_LD*4)   // 201728

__global__ void __launch_bounds__(256, 1)
dist_topk_kernel() {
    extern __shared__ char smem[];
    __half* As = (__half*)(smem + DT_AS_OFF);
    __half* Bs = (__half*)(smem + DT_BS_OFF);
    float* sq_s = (float*)(smem + DT_SQ_OFF);
    float* sd   = (float*)(smem + DT_SD_OFF);

    int t = threadIdx.x;
    int lane = t & 31, w = t >> 5;
    int wm = w & 3, wn = w >> 2;
    int b = blockIdx.y;
    int i0 = blockIdx.x * 128;

    const __half* F = g_f16 + (size_t)b * SEQ * DIM;
    const float* sqb = g_sq + (size_t)b * SEQ;

    // resident A strip: 128 x 256 fp16
    for (int idx = t; idx < 128 * 32; idx += 256) {
        int r = idx >> 5, c = (idx & 31) * 8;
        *(uint4*)(As + r * DT_LD + c) = *(const uint4*)(F + (size_t)(i0 + r) * 256 + c);
    }

    // per-thread running top-16 for row (t>>1), half (t&1)
    float tv[16]; int ti_[16];
#pragma unroll
    for (int n = 0; n < 16; n++) { tv[n] = CUDART_INF_F; ti_[n] = -1; }
    int srow = t >> 1, shalf = t & 1;
    const float* rowp = sd + srow * DT_SD_LD + shalf * 64;

    for (int jt = 0; jt < 32; jt++) {
        int j0 = jt * 128;
        if (t < 128) sq_s[t] = sqb[j0 + t];
        // full B tile: 128 x 256 fp16 (16 uint4 per thread)
#pragma unroll
        for (int q = 0; q < 16; q++) {
            int flat = t + q * 256;               // 4096 uint4
            int r = flat >> 5, c = (flat & 31) * 8;
            *(uint4*)(Bs + r * DT_LD + c) = *(const uint4*)(F + (size_t)(j0 + r) * 256 + c);
        }
        __syncthreads();   // B visible; also guarantees all threads done scanning previous sd

        float acc[2][8][4];
#pragma unroll
        for (int mi = 0; mi < 2; mi++)
#pragma unroll
            for (int nj = 0; nj < 8; nj++)
#pragma unroll
                for (int e = 0; e < 4; e++) acc[mi][nj][e] = 0.f;

#pragma unroll 1
        for (int kb = 0; kb < 256; kb += 32) {
#pragma unroll
            for (int kk = 0; kk < 32; kk += 16) {
                uint32_t a[2][4], bfr[8][2];
#pragma unroll
                for (int mi = 0; mi < 2; mi++) {
                    uint32_t addr = smem_u32(As + (wm*32 + mi*16 + (lane & 15)) * DT_LD + kb + kk + (lane >> 4) * 8);
                    ldsm_x4(addr, a[mi][0], a[mi][1], a[mi][2], a[mi][3]);
                }
#pragma unroll
                for (int g = 0; g < 4; g++) {
                    int nrow = wn*64 + g*16 + (lane & 7) + ((lane >> 4) << 3);
                    int ncol = kb + kk + ((lane >> 3) & 1) * 8;
                    uint32_t r0, r1, r2, r3;
                    ldsm_x4(smem_u32(Bs + nrow * DT_LD + ncol), r0, r1, r2, r3);
                    bfr[g*2][0] = r0; bfr[g*2][1] = r1;
                    bfr[g*2+1][0] = r2; bfr[g*2+1][1] = r3;
                }
#pragma unroll
                for (int mi = 0; mi < 2; mi++)
#pragma unroll
                    for (int nj = 0; nj < 8; nj++)
                        mma_fp16(acc[mi][nj], a[mi], bfr[nj]);
            }
        }

        // write keys into sd (own-warp fragments; no sync needed before)
#pragma unroll
        for (int mi = 0; mi < 2; mi++) {
            int r = wm*32 + mi*16 + (lane >> 2);
#pragma unroll
            for (int nj = 0; nj < 8; nj++) {
                int c = wn*64 + nj*8 + (lane & 3) * 2;
                float s0 = sq_s[c], s1 = sq_s[c + 1];
                sd[r * DT_SD_LD + c]           = s0 - 2.f * acc[mi][nj][0];
                sd[r * DT_SD_LD + c + 1]       = s1 - 2.f * acc[mi][nj][1];
                sd[(r + 8) * DT_SD_LD + c]     = s0 - 2.f * acc[mi][nj][2];
                sd[(r + 8) * DT_SD_LD + c + 1] = s1 - 2.f * acc[mi][nj][3];
            }
        }
        __syncthreads();   // sd complete

        // scan 64 keys of this thread's row-half, maintain top-16
        int jbase = j0 + shalf * 64;
#pragma unroll 4
        for (int j = 0; j < 64; j++) {
            float d = rowp[j];
            if (d < tv[15]) {
                float cv = d; int ci = jbase + j;
#pragma unroll
                for (int n = 0; n < 16; n++) {
                    if (cv < tv[n]) {
                        float tvv = tv[n]; tv[n] = cv; cv = tvv;
                        int tii = ti_[n]; ti_[n] = ci; ci = tii;
                    }
                }
            }
        }
        // no sync: next tile's post-B-load sync protects sd overwrite
    }

    // merge both halves' lists via smem (keys in sd[row][0..31], ids at [32..63])
    __syncthreads();
#pragma unroll
    for (int n = 0; n < 16; n++) {
        sd[srow * DT_SD_LD + shalf * 16 + n] = tv[n];
        ((int*)sd)[srow * DT_SD_LD + 32 + shalf * 16 + n] = ti_[n];
    }
    __syncthreads();
    if (t < 128) {
        float mv[16]; int mid[16];
#pragma unroll
        for (int n = 0; n < 16; n++) { mv[n] = CUDART_INF_F; mid[n] = -1; }
#pragma unroll
        for (int p = 0; p < 32; p++) {
            float d = sd[t * DT_SD_LD + p];
            if (d < mv[15]) {
                float cv = d; int ci = ((int*)sd)[t * DT_SD_LD + 32 + p];
#pragma unroll
                for (int n = 0; n < 16; n++) {
                    if (cv < mv[n]) {
                        float tvv = mv[n]; mv[n] = cv; cv = tvv;
                        int tii = mid[n]; mid[n] = ci; ci = tii;
                    }
                }
            }
        }
        size_t base = ((size_t)b * SEQ + i0 + t) * 16;
#pragma unroll
        for (int n = 0; n < 16; n++) g_idx[base + n] = b * SEQ + mid[n];
    }
}

// ---------------- bf16 tensor-core GEMM: C[Mx256] = A[Mx256] @ W[256x256] ----------------
template<bool HAS_BIAS, bool HAS_ADD, bool OUT_BF16>
__global__ void __launch_bounds__(256)
mma_gemm(const bf16* __restrict__ Ag, const bf16* __restrict__ Wg,
         const float* __restrict__ bias, const float* __restrict__ addsrc,
         void* __restrict__ Cout) {
    __shared__ bf16 As[128][40];
    __shared__ bf16 Ws_[32][136];
    int t = threadIdx.x;
    int lane = t & 31, w = t >> 5;
    int wm = w & 3, wn = w >> 2;
    int m0 = blockIdx.x * 128;
    int n0 = blockIdx.y * 128;

    float acc[2][8][4];
#pragma unroll
    for (int mi = 0; mi < 2; mi++)
#pragma unroll
        for (int nj = 0; nj < 8; nj++)
#pragma unroll
            for (int e = 0; e < 4; e++) acc[mi][nj][e] = 0.f;

    for (int kb = 0; kb < 256; kb += 32) {
#pragma unroll
        for (int q = 0; q < 2; q++) {
            int flat = t * 2 + q;
            int row = flat >> 2, col = (flat & 3) * 8;
            *(uint4*)&As[row][col] = *(const uint4*)(Ag + ((size_t)(m0 + row) * 256 + kb + col));
        }
#pragma unroll
        for (int q = 0; q < 2; q++) {
            int flat = t * 2 + q;
            int row = flat >> 4, col = (flat & 15) * 8;
            *(uint4*)&Ws_[row][col] = *(const uint4*)(Wg + ((size_t)(kb + row) * 256 + n0 + col));
        }
        __syncthreads();
#pragma unroll
        for (int kk = 0; kk < 32; kk += 16) {
            uint32_t a[2][4], bfr[8][2];
#pragma unroll
            for (int mi = 0; mi < 2; mi++) {
                uint32_t addr = smem_u32(&As[wm*32 + mi*16 + (lane & 15)][kk + (lane >> 4) * 8]);
                ldsm_x4(addr, a[mi][0], a[mi][1], a[mi][2], a[mi][3]);
            }
#pragma unroll
            for (int g = 0; g < 4; g++) {
                uint32_t r0, r1, r2, r3;
                uint32_t addr = smem_u32(&Ws_[kk + (lane & 15)][wn*64 + g*16 + (lane >> 4) * 8]);
                ldsm_x4_t(addr, r0, r1, r2, r3);
                bfr[g*2][0] = r0; bfr[g*2][1] = r1;
                bfr[g*2+1][0] = r2; bfr[g*2+1][1] = r3;
            }
#pragma unroll
            for (int mi = 0; mi < 2; mi++)
#pragma unroll
                for (int nj = 0; nj < 8; nj++)
                    mma_bf16(acc[mi][nj], a[mi], bfr[nj]);
        }
        __syncthreads();
    }

#pragma unroll
    for (int mi = 0; mi < 2; mi++) {
#pragma unroll
        for (int nj = 0; nj < 8; nj++) {
            int r = m0 + wm*32 + mi*16 + (lane >> 2);
            int cc = n0 + wn*64 + nj*8 + (lane & 3) * 2;
            float v0 = acc[mi][nj][0], v1 = acc[mi][nj][1];
            float v2 = acc[mi][nj][2], v3 = acc[mi][nj][3];
            if (HAS_BIAS) {
                float b0 = bias[cc], b1 = bias[cc+1];
                v0 += b0; v1 += b1; v2 += b0; v3 += b1;
            }
            if (HAS_ADD) {
                v0 += addsrc[(size_t)r*256 + cc];     v1 += addsrc[(size_t)r*256 + cc + 1];
                v2 += addsrc[(size_t)(r+8)*256 + cc]; v3 += addsrc[(size_t)(r+8)*256 + cc + 1];
            }
            if (OUT_BF16) {
                bf16* C = (bf16*)Cout;
                __nv_bfloat162 o0, o1;
                o0.x = __float2bfloat16_rn(v0); o0.y = __float2bfloat16_rn(v1);
                o1.x = __float2bfloat16_rn(v2); o1.y = __float2bfloat16_rn(v3);
                *(__nv_bfloat162*)(C + (size_t)r*256 + cc) = o0;
                *(__nv_bfloat162*)(C + (size_t)(r+8)*256 + cc) = o1;
            } else {
                float* C = (float*)Cout;
                float2 o0 = {v0, v1}, o1 = {v2, v3};
                *(float2*)(C + (size_t)r*256 + cc) = o0;
                *(float2*)(C + (size_t)(r+8)*256 + cc) = o1;
            }
        }
    }
}

// ---------------- fused 3-projection GEMM: {vf, qg(+g1_b), kg1} = h @ {wv, wq1, wk1} ----------------
struct Proj3Args { const bf16* w[3]; bf16* d[3]; const float* bias; };
__global__ void __launch_bounds__(256)
mma_gemm_proj3(const bf16* __restrict__ Ag, Proj3Args pa) {
    __shared__ bf16 As[128][40];
    __shared__ bf16 Ws_[32][136];
    int t = threadIdx.x;
    int lane = t & 31, w = t >> 5;
    int wm = w & 3, wn = w >> 2;
    int m0 = blockIdx.x * 128;
    int wi = blockIdx.y >> 1;
    int n0 = (blockIdx.y & 1) * 128;
    const bf16* Wg = pa.w[wi];
    bf16* C = pa.d[wi];
    bool has_bias = (wi == 1);

    float acc[2][8][4];
#pragma unroll
    for (int mi = 0; mi < 2; mi++)
#pragma unroll
        for (int nj = 0; nj < 8; nj++)
#pragma unroll
            for (int e = 0; e < 4; e++) acc[mi][nj][e] = 0.f;

    for (int kb = 0; kb < 256; kb += 32) {
#pragma unroll
        for (int q = 0; q < 2; q++) {
            int flat = t * 2 + q;
            int row = flat >> 2, col = (flat & 3) * 8;
            *(uint4*)&As[row][col] = *(const uint4*)(Ag + ((size_t)(m0 + row) * 256 + kb + col));
        }
#pragma unroll
        for (int q = 0; q < 2; q++) {
            int flat = t * 2 + q;
            int row = flat >> 4, col = (flat & 15) * 8;
            *(uint4*)&Ws_[row][col] = *(const uint4*)(Wg + ((size_t)(kb + row) * 256 + n0 + col));
        }
        __syncthreads();
#pragma unroll
        for (int kk = 0; kk < 32; kk += 16) {
            uint32_t a[2][4], bfr[8][2];
#pragma unroll
            for (int mi = 0; mi < 2; mi++) {
                uint32_t addr = smem_u32(&As[wm*32 + mi*16 + (lane & 15)][kk + (lane >> 4) * 8]);
                ldsm_x4(addr, a[mi][0], a[mi][1], a[mi][2], a[mi][3]);
            }
#pragma unroll
            for (int g = 0; g < 4; g++) {
                uint32_t r0, r1, r2, r3;
                uint32_t addr = smem_u32(&Ws_[kk + (lane & 15)][wn*64 + g*16 + (lane >> 4) * 8]);
                ldsm_x4_t(addr, r0, r1, r2, r3);
                bfr[g*2][0] = r0; bfr[g*2][1] = r1;
                bfr[g*2+1][0] = r2; bfr[g*2+1][1] = r3;
            }
#pragma unroll
            for (int mi = 0; mi < 2; mi++)
#pragma unroll
                for (int nj = 0; nj < 8; nj++)
                    mma_bf16(acc[mi][nj], a[mi], bfr[nj]);
        }
        __syncthreads();
    }

#pragma unroll
    for (int mi = 0; mi < 2; mi++) {
#pragma unroll
        for (int nj = 0; nj < 8; nj++) {
            int r = m0 + wm*32 + mi*16 + (lane >> 2);
            int cc = n0 + wn*64 + nj*8 + (lane & 3) * 2;
            float v0 = acc[mi][nj][0], v1 = acc[mi][nj][1];
            float v2 = acc[mi][nj][2], v3 = acc[mi][nj][3];
            if (has_bias) {
                float b0 = pa.bias[cc], b1 = pa.bias[cc+1];
                v0 += b0; v1 += b1; v2 += b0; v3 += b1;
            }
            __nv_bfloat162 o0, o1;
            o0.x = __float2bfloat16_rn(v0); o0.y = __float2bfloat16_rn(v1);
            o1.x = __float2bfloat16_rn(v2); o1.y = __float2bfloat16_rn(v3);
            *(__nv_bfloat162*)(C + (size_t)r*256 + cc) = o0;
            *(__nv_bfloat162*)(C + (size_t)(r+8)*256 + cc) = o1;
        }
    }
}

// ---------------- fused attention: R-build + R@g2 + softmax + v-contraction ----------------
__global__ void __launch_bounds__(512, 1)
attn_fused_kernel() {
    __shared__ bf16 Rs[128][40];
    __shared__ bf16 Ws_[32][264];
    __shared__ int  nbr[128];

    int t = threadIdx.x;
    int lane = t & 31, w = t >> 5;
    int wm = w & 3, wn = w >> 2;
    int m0 = blockIdx.x * 128;

    if (t < 128) nbr[t] = g_idx[m0 + t];
    __syncthreads();

    float acc[2][8][4];
#pragma unroll
    for (int mi = 0; mi < 2; mi++)
#pragma unroll
        for (int nj = 0; nj < 8; nj++)
#pragma unroll
            for (int e = 0; e < 4; e++) acc[mi][nj][e] = 0.f;

    int rrow = t >> 2;
    int cg = (t & 3) * 8;
    int pt_r = (m0 + rrow) >> 4;
    int nr_r = nbr[rrow];
    const uint4* qrow = (const uint4*)(g_qgb  + (size_t)pt_r * 256);
    const uint4* krow = (const uint4*)(g_kg1b + (size_t)nr_r * 256);
    __nv_bfloat162 z2 = __float2bfloat162_rn(0.f);

    for (int kb = 0; kb < 256; kb += 32) {
        {
            uint4 qv = qrow[(kb + cg) >> 3];
            uint4 kv = krow[(kb + cg) >> 3];
            const __nv_bfloat162* qp = (const __nv_bfloat162*)&qv;
            const __nv_bfloat162* kp = (const __nv_bfloat162*)&kv;
            uint4 ov;
            __nv_bfloat162* op = (__nv_bfloat162*)&ov;
#pragma unroll
            for (int e = 0; e < 4; e++)
                op[e] = __hmax2(__hsub2(qp[e], kp[e]), z2);
            *(uint4*)&Rs[rrow][cg] = ov;
        }
#pragma unroll
        for (int q = 0; q < 2; q++) {
            int flat = t * 2 + q;
            int row = flat >> 5, col = (flat & 31) * 8;
            *(uint4*)&Ws_[row][col] = *(const uint4*)(g_g2b + (size_t)(kb + row) * 256 + col);
        }
        __syncthreads();
#pragma unroll
        for (int kk = 0; kk < 32; kk += 16) {
            uint32_t a[2][4], bfr[8][2];
#pragma unroll
            for (int mi = 0; mi < 2; mi++) {
                uint32_t addr = smem_u32(&Rs[wm*32 + mi*16 + (lane & 15)][kk + (lane >> 4) * 8]);
                ldsm_x4(addr, a[mi][0], a[mi][1], a[mi][2], a[mi][3]);
            }
#pragma unroll
            for (int g = 0; g < 4; g++) {
                uint32_t r0, r1, r2, r3;
                uint32_t addr = smem_u32(&Ws_[kk + (lane & 15)][wn*64 + g*16 + (lane >> 4) * 8]);
                ldsm_x4_t(addr, r0, r1, r2, r3);
                bfr[g*2][0] = r0; bfr[g*2][1] = r1;
                bfr[g*2+1][0] = r2; bfr[g*2+1][1] = r3;
            }
#pragma unroll
            for (int mi = 0; mi < 2; mi++)
#pragma unroll
                for (int nj = 0; nj < 8; nj++)
                    mma_bf16(acc[mi][nj], a[mi], bfr[nj]);
        }
        __syncthreads();
    }

    const float inv = 0.0625f;
#pragma unroll
    for (int mi = 0; mi < 2; mi++) {
        int lrow = wm * 32 + mi * 16;
        int ptm = (m0 + lrow) >> 4;
        int nrA = nbr[lrow + (lane >> 2)];
        int nrB = nbr[lrow + 8 + (lane >> 2)];
#pragma unroll
        for (int nj = 0; nj < 8; nj++) {
            int cc = wn * 64 + nj * 8 + (lane & 3) * 2;
            float x0 = acc[mi][nj][0], x1 = acc[mi][nj][1];
            float x2 = acc[mi][nj][2], x3 = acc[mi][nj][3];
            float mA = fmaxf(x0, x2), mB = fmaxf(x1, x3);
#pragma unroll
            for (int off = 4; off <= 16; off <<= 1) {
                mA = fmaxf(mA, __shfl_xor_sync(0xffffffffu, mA, off));
                mB = fmaxf(mB, __shfl_xor_sync(0xffffffffu, mB, off));
            }
            float e0 = __expf((x0 - mA) * inv), e2 = __expf((x2 - mA) * inv);
            float e1 = __expf((x1 - mB) * inv), e3 = __expf((x3 - mB) * inv);
            __nv_bfloat162 vA = *(const __nv_bfloat162*)(g_vf + (size_t)nrA * 256 + cc);
            __nv_bfloat162 vB = *(const __nv_bfloat162*)(g_vf + (size_t)nrB * 256 + cc);
            float sA = e0 + e2, sB = e1 + e3;
            float wA = e0 * __bfloat162float(vA.x) + e2 * __bfloat162float(vB.x);
            float wB = e1 * __bfloat162float(vA.y) + e3 * __bfloat162float(vB.y);
#pragma unroll
            for (int off = 4; off <= 16; off <<= 1) {
                sA += __shfl_xor_sync(0xffffffffu, sA, off);
                sB += __shfl_xor_sync(0xffffffffu, sB, off);
                wA += __shfl_xor_sync(0xffffffffu, wA, off);
                wB += __shfl_xor_sync(0xffffffffu, wB, off);
            }
            if ((lane >> 2) == 0) {
                __nv_bfloat162 o;
                o.x = __float2bfloat16_rn(wA / sA);
                o.y = __float2bfloat16_rn(wB / sB);
                *(__nv_bfloat162*)(g_resb + (size_t)ptm * 256 + cc) = o;
            }
        }
    }
}

// ---------------- launch ----------------
extern "C" void kernel_launch(void* const* d_in, const int* in_sizes, int n_in,
                              void* d_out, int out_size) {
    const float* x     = (const float*)d_in[0];
    const float* fc1_w = (const float*)d_in[1];
    const float* fc1_b = (const float*)d_in[2];
    const float* fc2_w = (const float*)d_in[3];
    const float* fc2_b = (const float*)d_in[4];
    const float* wq_w  = (const float*)d_in[5];
    const float* wk_w  = (const float*)d_in[6];
    const float* wv_w  = (const float*)d_in[7];
    const float* g1_w  = (const float*)d_in[8];
    const float* g1_b  = (const float*)d_in[9];
    const float* g2_w  = (const float*)d_in[10];
    const float* g2_b  = (const float*)d_in[11];  (void)g2_b;
    float* out = (float*)d_out;

    bf16 *p_fc1b, *p_wqb, *p_wkb, *p_wvb, *p_g1b, *p_g2b, *p_fc2b, *p_wq1, *p_wk1;
    bf16 *p_fhi, *p_h, *p_vf, *p_qgb, *p_kg1b, *p_resb;
    float *p_feat;
    cudaGetSymbolAddress((void**)&p_fc1b, g_fc1b);
    cudaGetSymbolAddress((void**)&p_wqb,  g_wqb);
    cudaGetSymbolAddress((void**)&p_wkb,  g_wkb);
    cudaGetSymbolAddress((void**)&p_wvb,  g_wvb);
    cudaGetSymbolAddress((void**)&p_g1b,  g_g1b);
    cudaGetSymbolAddress((void**)&p_g2b,  g_g2b);
    cudaGetSymbolAddress((void**)&p_fc2b, g_fc2b);
    cudaGetSymbolAddress((void**)&p_wq1,  g_wq1);
    cudaGetSymbolAddress((void**)&p_wk1,  g_wk1);
    cudaGetSymbolAddress((void**)&p_fhi,  g_fhi);
    cudaGetSymbolAddress((void**)&p_h,    g_h);
    cudaGetSymbolAddress((void**)&p_vf,   g_vf);
    cudaGetSymbolAddress((void**)&p_qgb,  g_qgb);
    cudaGetSymbolAddress((void**)&p_kg1b, g_kg1b);
    cudaGetSymbolAddress((void**)&p_resb, g_resb);
    cudaGetSymbolAddress((void**)&p_feat, g_feat);

    static int s_init_done = 0;
    static cudaStream_t s1;
    static cudaEvent_t e0, e1;
    if (!s_init_done) {
        cudaFuncSetAttribute(dist_topk_kernel,
                             cudaFuncAttributeMaxDynamicSharedMemorySize, DT_SMEM_SZ);
        cudaStreamCreateWithFlags(&s1, cudaStreamNonBlocking);
        cudaEventCreateWithFlags(&e0, cudaEventDisableTiming);
        cudaEventCreateWithFlags(&e1, cudaEventDisableTiming);
        s_init_done = 1;
    }

    CvtArgs ca;
    ca.s[0] = fc1_w; ca.d[0] = p_fc1b;
    ca.s[1] = wq_w;  ca.d[1] = p_wqb;
    ca.s[2] = wk_w;  ca.d[2] = p_wkb;
    ca.s[3] = wv_w;  ca.d[3] = p_wvb;
    ca.s[4] = g1_w;  ca.d[4] = p_g1b;
    ca.s[5] = g2_w;  ca.d[5] = p_g2b;
    ca.s[6] = fc2_w; ca.d[6] = p_fc2b;
    cvt_all_kernel<<<7*64, 256>>>(ca);

    prep_kernel<<<NPTS, 256>>>(x, out);

    // fork: distance + top-K on side stream, concurrent with the GEMM chain
    cudaEventRecord(e0, 0);
    cudaStreamWaitEvent(s1, e0, 0);
    dist_topk_kernel<<<dim3(32, BATCH), 256, DT_SMEM_SZ, s1>>>();
    cudaEventRecord(e1, s1);

    // main stream: composed weights + h + 3 projections (independent of dist)
    mma_gemm<false, false, true><<<dim3(2, 2), 256>>>(p_wqb, p_g1b, nullptr, nullptr, p_wq1);
    mma_gemm<false, false, true><<<dim3(2, 2), 256>>>(p_wkb, p_g1b, nullptr, nullptr, p_wk1);
    mma_gemm<true,  false, true><<<dim3(NPTS/128, 2), 256>>>(p_fhi, p_fc1b, fc1_b, nullptr, p_h);

    Proj3Args pa;
    pa.w[0] = p_wvb; pa.d[0] = p_vf;
    pa.w[1] = p_wq1; pa.d[1] = p_qgb;
    pa.w[2] = p_wk1; pa.d[2] = p_kg1b;
    pa.bias = g1_b;
    mma_gemm_proj3<<<dim3(NPTS/128, 6), 256>>>(p_h, pa);

    // join: attention tail needs g_idx
    cudaStreamWaitEvent(0, e1, 0);
    attn_fused_kernel<<<(NPTS*KNN)/128, 512>>>();

    // out = res@fc2 + fc2_b + feat
    mma_gemm<true, true, false><<<dim3(NPTS/128, 2), 256>>>(p_resb, p_fc2b, fc2_b, p_feat, out + (size_t)NPTS*3);
}